// round 1
// baseline (speedup 1.0000x reference)
#include <cuda_runtime.h>
#include <cuda_bf16.h>
#include <math_constants.h>

// Problem constants
#define T 2048
#define D 1024
#define H 16
#define DH 64
#define D3 3072
#define D2 2048
#define DFF 4096
#define LN_EPS 1e-5f
#define SPARSITY_LAMBDA 0.0005f

// ---------------- scratch (static device globals; no runtime alloc) ----------------
__device__ float g_xn[(size_t)T * D];          // 8 MB
__device__ float g_qkv[(size_t)T * D3];        // 24 MB
__device__ float g_S[(size_t)H * T * T];       // 256 MB  (scores -> P_txt in place)
__device__ float g_P2[(size_t)H * T * T];      // 256 MB  (P_cau)
__device__ float g_cat[(size_t)T * D2];        // 16 MB
__device__ float g_tmp[(size_t)T * D];         // 8 MB
__device__ float g_h[(size_t)T * D];           // 8 MB
__device__ float g_hn[(size_t)T * D];          // 8 MB
__device__ float g_ff[(size_t)T * DFF];        // 32 MB
__device__ double g_sigacc;

// ---------------- utilities ----------------
__device__ __forceinline__ float blockReduceSum(float v) {
    __shared__ float red[32];
    int lane = threadIdx.x & 31, wid = threadIdx.x >> 5;
    #pragma unroll
    for (int o = 16; o > 0; o >>= 1) v += __shfl_xor_sync(0xffffffff, v, o);
    __syncthreads();
    if (lane == 0) red[wid] = v;
    __syncthreads();
    int nw = (blockDim.x + 31) >> 5;
    float r = (threadIdx.x < nw) ? red[threadIdx.x] : 0.f;
    if (wid == 0) {
        #pragma unroll
        for (int o = 16; o > 0; o >>= 1) r += __shfl_xor_sync(0xffffffff, r, o);
        if (lane == 0) red[0] = r;
    }
    __syncthreads();
    return red[0];
}

__device__ __forceinline__ float blockReduceMax(float v) {
    __shared__ float red[32];
    int lane = threadIdx.x & 31, wid = threadIdx.x >> 5;
    #pragma unroll
    for (int o = 16; o > 0; o >>= 1) v = fmaxf(v, __shfl_xor_sync(0xffffffff, v, o));
    __syncthreads();
    if (lane == 0) red[wid] = v;
    __syncthreads();
    int nw = (blockDim.x + 31) >> 5;
    float r = (threadIdx.x < nw) ? red[threadIdx.x] : -CUDART_INF_F;
    if (wid == 0) {
        #pragma unroll
        for (int o = 16; o > 0; o >>= 1) r = fmaxf(r, __shfl_xor_sync(0xffffffff, r, o));
        if (lane == 0) red[0] = r;
    }
    __syncthreads();
    return red[0];
}

// ---------------- layernorm ----------------
__global__ __launch_bounds__(256) void k_layernorm(
    const float* __restrict__ x, const float* __restrict__ g,
    const float* __restrict__ b, float* __restrict__ out)
{
    int t = blockIdx.x;
    const float* xr = x + (size_t)t * D;
    float s = 0.f, s2 = 0.f;
    for (int i = threadIdx.x; i < D; i += 256) {
        float v = xr[i];
        s += v; s2 += v * v;
    }
    float tot = blockReduceSum(s);
    float tot2 = blockReduceSum(s2);
    float mean = tot * (1.f / D);
    float var = tot2 * (1.f / D) - mean * mean;
    float rstd = rsqrtf(var + LN_EPS);
    float* orow = out + (size_t)t * D;
    for (int i = threadIdx.x; i < D; i += 256) {
        orow[i] = (xr[i] - mean) * rstd * g[i] + b[i];
    }
}

// ---------------- GEMM NT: C[m,n] = scale * sum_k A[m,k]*B[n,k] (+bias)(gelu)(+res) ----------------
// 64x64 tile, BK=16, 256 threads, 4x4 micro-tile. All dims multiples of 64/16.
template<bool GELU>
__global__ __launch_bounds__(256) void k_gemm_nt(
    const float* __restrict__ A, int lda, long long aHead,
    const float* __restrict__ B, int ldb, long long bHead,
    float* __restrict__ C, int ldc, long long cHead,
    int M, int N, int K, float scale,
    const float* __restrict__ bias,
    const float* __restrict__ res, int ldres,
    int causal)
{
    int m0 = blockIdx.y * 64, n0 = blockIdx.x * 64;
    if (causal && n0 > m0) return;
    A += (long long)blockIdx.z * aHead;
    B += (long long)blockIdx.z * bHead;
    C += (long long)blockIdx.z * cHead;

    __shared__ float As[16][64];
    __shared__ float Bs[16][64];

    int tid = threadIdx.x;
    int lrow = tid >> 2;           // 0..63
    int lkq = (tid & 3) << 2;      // 0,4,8,12
    int tx = tid & 15, ty = tid >> 4;

    float acc[4][4] = {};

    for (int k0 = 0; k0 < K; k0 += 16) {
        float4 a4 = *(const float4*)(A + (long long)(m0 + lrow) * lda + k0 + lkq);
        float4 b4 = *(const float4*)(B + (long long)(n0 + lrow) * ldb + k0 + lkq);
        As[lkq + 0][lrow] = a4.x; As[lkq + 1][lrow] = a4.y;
        As[lkq + 2][lrow] = a4.z; As[lkq + 3][lrow] = a4.w;
        Bs[lkq + 0][lrow] = b4.x; Bs[lkq + 1][lrow] = b4.y;
        Bs[lkq + 2][lrow] = b4.z; Bs[lkq + 3][lrow] = b4.w;
        __syncthreads();
        #pragma unroll
        for (int k = 0; k < 16; k++) {
            float4 av = *(const float4*)&As[k][ty * 4];
            float4 bv = *(const float4*)&Bs[k][tx * 4];
            float a[4] = {av.x, av.y, av.z, av.w};
            float b[4] = {bv.x, bv.y, bv.z, bv.w};
            #pragma unroll
            for (int i = 0; i < 4; i++)
                #pragma unroll
                for (int j = 0; j < 4; j++)
                    acc[i][j] += a[i] * b[j];
        }
        __syncthreads();
    }

    #pragma unroll
    for (int i = 0; i < 4; i++) {
        int m = m0 + ty * 4 + i;
        #pragma unroll
        for (int j = 0; j < 4; j++) {
            int n = n0 + tx * 4 + j;
            float v = acc[i][j] * scale;
            if (bias) v += bias[n];
            if (GELU) v = 0.5f * v * (1.f + erff(v * 0.70710678118654752f));
            if (res) v += res[(long long)m * ldres + n];
            C[(long long)m * ldc + n] = v;
        }
    }
}

// ---------------- GEMM NN: C[m,n] = sum_k A[m,k]*B[k,n]; N tile = 64 ----------------
__global__ __launch_bounds__(256) void k_gemm_nn(
    const float* __restrict__ A, int lda, long long aHead,
    const float* __restrict__ B, int ldb, long long bHead,
    float* __restrict__ C, int ldc, long long cHead,
    int M, int K, int causal)
{
    int m0 = blockIdx.y * 64;
    A += (long long)blockIdx.z * aHead;
    B += (long long)blockIdx.z * bHead;
    C += (long long)blockIdx.z * cHead;

    int Keff = causal ? min(K, m0 + 64) : K;

    __shared__ float As[16][64];
    __shared__ float Bs[16][64];

    int tid = threadIdx.x;
    int lrow = tid >> 2;
    int lkq = (tid & 3) << 2;
    int br = tid >> 4;             // 0..15 (k row)
    int bc = (tid & 15) << 2;      // 0..60 (n col)
    int tx = tid & 15, ty = tid >> 4;

    float acc[4][4] = {};

    for (int k0 = 0; k0 < Keff; k0 += 16) {
        float4 a4 = *(const float4*)(A + (long long)(m0 + lrow) * lda + k0 + lkq);
        As[lkq + 0][lrow] = a4.x; As[lkq + 1][lrow] = a4.y;
        As[lkq + 2][lrow] = a4.z; As[lkq + 3][lrow] = a4.w;
        float4 b4 = *(const float4*)(B + (long long)(k0 + br) * ldb + bc);
        *(float4*)&Bs[br][bc] = b4;
        __syncthreads();
        #pragma unroll
        for (int k = 0; k < 16; k++) {
            float4 av = *(const float4*)&As[k][ty * 4];
            float4 bv = *(const float4*)&Bs[k][tx * 4];
            float a[4] = {av.x, av.y, av.z, av.w};
            float b[4] = {bv.x, bv.y, bv.z, bv.w};
            #pragma unroll
            for (int i = 0; i < 4; i++)
                #pragma unroll
                for (int j = 0; j < 4; j++)
                    acc[i][j] += a[i] * b[j];
        }
        __syncthreads();
    }

    #pragma unroll
    for (int i = 0; i < 4; i++) {
        int m = m0 + ty * 4 + i;
        #pragma unroll
        for (int j = 0; j < 4; j++) {
            int n = tx * 4 + j;
            C[(long long)m * ldc + n] = acc[i][j];
        }
    }
}

// ---------------- dual softmax + sigmoid-mean accumulation ----------------
// grid (T, H). Row t of head h. P_txt overwrites g_S; P_cau -> g_P2.
__global__ __launch_bounds__(256) void k_softmax2(const float* __restrict__ lm)
{
    __shared__ float sS[T];
    __shared__ float sG[T];
    int t = blockIdx.x, h = blockIdx.y;
    long long roff = ((long long)h * T + t) * (long long)T;
    float* Sr = g_S + roff;
    float* P2r = g_P2 + roff;
    const float* lmr = lm + roff;

    float sigsum = 0.f, m1 = -CUDART_INF_F, m2 = -CUDART_INF_F;
    for (int s = threadIdx.x; s < T; s += 256) {
        float v = Sr[s];
        float sg = 1.f / (1.f + __expf(-lmr[s]));
        sS[s] = v; sG[s] = sg;
        sigsum += sg;
        if (s <= t) {
            m1 = fmaxf(m1, v);
            m2 = fmaxf(m2, v * sg);
        }
    }
    float tot_sig = blockReduceSum(sigsum);
    if (threadIdx.x == 0) atomicAdd(&g_sigacc, (double)tot_sig);
    m1 = blockReduceMax(m1);
    m2 = blockReduceMax(m2);

    float e1s = 0.f, e2s = 0.f;
    for (int s = threadIdx.x; s <= t; s += 256) {
        e1s += __expf(sS[s] - m1);
        e2s += __expf(sS[s] * sG[s] - m2);
    }
    float sum1 = blockReduceSum(e1s);
    float sum2 = blockReduceSum(e2s);
    float r1 = 1.f / sum1, r2 = 1.f / sum2;

    int end = min(T, ((t >> 6) + 1) << 6);   // zero up to next 64-boundary (AV reads it)
    for (int s = threadIdx.x; s < end; s += 256) {
        float p1 = 0.f, p2 = 0.f;
        if (s <= t) {
            p1 = __expf(sS[s] - m1) * r1;
            p2 = __expf(sS[s] * sG[s] - m2) * r2;
        }
        Sr[s] = p1;
        P2r[s] = p2;
    }
}

__global__ void k_zero_acc() { g_sigacc = 0.0; }

__global__ void k_write_sp(float* out, int out_size)
{
    const long long TD = (long long)T * D;
    if (out_size > TD) {
        double mean = g_sigacc / ((double)H * (double)T * (double)T);
        out[TD] = (float)(SPARSITY_LAMBDA * mean);
    }
}

// ---------------- launch ----------------
extern "C" void kernel_launch(void* const* d_in, const int* in_sizes, int n_in,
                              void* d_out, int out_size)
{
    const float* x      = (const float*)d_in[0];
    // d_in[1] = causal_mask (implicit triu, unused)
    const float* W_qkv  = (const float*)d_in[2];
    const float* W_out  = (const float*)d_in[3];
    const float* logm   = (const float*)d_in[4];
    const float* W_gate = (const float*)d_in[5];
    const float* b_gate = (const float*)d_in[6];
    const float* g1     = (const float*)d_in[7];
    const float* b1     = (const float*)d_in[8];
    const float* g2     = (const float*)d_in[9];
    const float* b2     = (const float*)d_in[10];
    const float* W_ff1  = (const float*)d_in[11];
    const float* b_ff1  = (const float*)d_in[12];
    const float* W_ff2  = (const float*)d_in[13];
    const float* b_ff2  = (const float*)d_in[14];
    float* out = (float*)d_out;

    float *xn, *qkv, *S, *P2, *cat, *tmp, *hbuf, *hn, *ff;
    cudaGetSymbolAddress((void**)&xn,   g_xn);
    cudaGetSymbolAddress((void**)&qkv,  g_qkv);
    cudaGetSymbolAddress((void**)&S,    g_S);
    cudaGetSymbolAddress((void**)&P2,   g_P2);
    cudaGetSymbolAddress((void**)&cat,  g_cat);
    cudaGetSymbolAddress((void**)&tmp,  g_tmp);
    cudaGetSymbolAddress((void**)&hbuf, g_h);
    cudaGetSymbolAddress((void**)&hn,   g_hn);
    cudaGetSymbolAddress((void**)&ff,   g_ff);

    k_zero_acc<<<1, 1>>>();

    // ln1
    k_layernorm<<<T, 256>>>(x, g1, b1, xn);

    // qkv = xn @ W_qkv^T   [2048 x 3072]
    k_gemm_nt<false><<<dim3(D3 / 64, T / 64, 1), 256>>>(
        xn, D, 0, W_qkv, D, 0, qkv, D3, 0, T, D3, D, 1.f, nullptr, nullptr, 0, 0);

    // scores per head: S = Q K^T / 8  (causal-skipped blocks)
    k_gemm_nt<false><<<dim3(T / 64, T / 64, H), 256>>>(
        qkv, D3, DH, qkv + D, D3, DH, S, T, (long long)T * T,
        T, T, DH, 0.125f, nullptr, nullptr, 0, 1);

    // dual softmax + sigmoid mean
    k_softmax2<<<dim3(T, H), 256>>>(logm);

    // out_txt = P_txt @ V  -> cat[:, h*64 + ...]
    k_gemm_nn<<<dim3(1, T / 64, H), 256>>>(
        S, T, (long long)T * T, qkv + 2 * D, D3, DH, cat, D2, DH, T, T, 1);
    // out_cau = P_cau @ V  -> cat[:, 1024 + h*64 + ...]
    k_gemm_nn<<<dim3(1, T / 64, H), 256>>>(
        P2, T, (long long)T * T, qkv + 2 * D, D3, DH, cat + D, D2, DH, T, T, 1);

    // tmp = cat @ W_gate^T + b_gate   [2048 x 1024]
    k_gemm_nt<false><<<dim3(D / 64, T / 64, 1), 256>>>(
        cat, D2, 0, W_gate, D2, 0, tmp, D, 0, T, D, D2, 1.f, b_gate, nullptr, 0, 0);

    // h = x + tmp @ W_out^T
    k_gemm_nt<false><<<dim3(D / 64, T / 64, 1), 256>>>(
        tmp, D, 0, W_out, D, 0, hbuf, D, 0, T, D, D, 1.f, nullptr, x, D, 0);

    // ln2
    k_layernorm<<<T, 256>>>(hbuf, g2, b2, hn);

    // ff = gelu(hn @ W_ff1^T + b_ff1)   [2048 x 4096]
    k_gemm_nt<true><<<dim3(DFF / 64, T / 64, 1), 256>>>(
        hn, D, 0, W_ff1, D, 0, ff, DFF, 0, T, DFF, D, 1.f, b_ff1, nullptr, 0, 0);

    // out = h + ff @ W_ff2^T + b_ff2
    k_gemm_nt<false><<<dim3(D / 64, T / 64, 1), 256>>>(
        ff, DFF, 0, W_ff2, DFF, 0, out, D, 0, T, D, DFF, 1.f, b_ff2, hbuf, D, 0);

    k_write_sp<<<1, 1>>>(out, out_size);
}

// round 2
// speedup vs baseline: 2.2060x; 2.2060x over previous
#include <cuda_runtime.h>
#include <cuda_bf16.h>
#include <math_constants.h>
#include <cstdint>

// Problem constants
#define T 2048
#define D 1024
#define H 16
#define DH 64
#define D3 3072
#define D2 2048
#define DFF 4096
#define LN_EPS 1e-5f
#define SPARSITY_LAMBDA 0.0005f

// ---------------- scratch ----------------
__device__ float g_xn[(size_t)T * D];
__device__ float g_qkv[(size_t)T * D3];
__device__ float g_S[(size_t)H * T * T];
__device__ float g_P2[(size_t)H * T * T];
__device__ float g_cat[(size_t)T * D2];
__device__ float g_tmp[(size_t)T * D];
__device__ float g_h[(size_t)T * D];
__device__ float g_hn[(size_t)T * D];
__device__ float g_ff[(size_t)T * DFF];
__device__ double g_sigacc;

// ---------------- helpers ----------------
__device__ __forceinline__ uint32_t f2tf(float f) {
    uint32_t u;
    asm("cvt.rna.tf32.f32 %0, %1;" : "=r"(u) : "f"(f));
    return u;
}

__device__ __forceinline__ void mma_tf32(float (&d)[4], const uint32_t (&a)[4], const uint32_t (&b)[2]) {
    asm volatile(
        "mma.sync.aligned.m16n8k8.row.col.f32.tf32.tf32.f32 "
        "{%0,%1,%2,%3}, {%4,%5,%6,%7}, {%8,%9}, {%0,%1,%2,%3};\n"
        : "+f"(d[0]), "+f"(d[1]), "+f"(d[2]), "+f"(d[3])
        : "r"(a[0]), "r"(a[1]), "r"(a[2]), "r"(a[3]), "r"(b[0]), "r"(b[1]));
}

__device__ __forceinline__ float blockReduceSum(float v) {
    __shared__ float red[32];
    int lane = threadIdx.x & 31, wid = threadIdx.x >> 5;
    #pragma unroll
    for (int o = 16; o > 0; o >>= 1) v += __shfl_xor_sync(0xffffffff, v, o);
    __syncthreads();
    if (lane == 0) red[wid] = v;
    __syncthreads();
    int nw = (blockDim.x + 31) >> 5;
    float r = (threadIdx.x < nw) ? red[threadIdx.x] : 0.f;
    if (wid == 0) {
        #pragma unroll
        for (int o = 16; o > 0; o >>= 1) r += __shfl_xor_sync(0xffffffff, r, o);
        if (lane == 0) red[0] = r;
    }
    __syncthreads();
    return red[0];
}

__device__ __forceinline__ float blockReduceMax(float v) {
    __shared__ float red[32];
    int lane = threadIdx.x & 31, wid = threadIdx.x >> 5;
    #pragma unroll
    for (int o = 16; o > 0; o >>= 1) v = fmaxf(v, __shfl_xor_sync(0xffffffff, v, o));
    __syncthreads();
    if (lane == 0) red[wid] = v;
    __syncthreads();
    int nw = (blockDim.x + 31) >> 5;
    float r = (threadIdx.x < nw) ? red[threadIdx.x] : -CUDART_INF_F;
    if (wid == 0) {
        #pragma unroll
        for (int o = 16; o > 0; o >>= 1) r = fmaxf(r, __shfl_xor_sync(0xffffffff, r, o));
        if (lane == 0) red[0] = r;
    }
    __syncthreads();
    return red[0];
}

// ---------------- layernorm ----------------
__global__ __launch_bounds__(256) void k_layernorm(
    const float* __restrict__ x, const float* __restrict__ g,
    const float* __restrict__ b, float* __restrict__ out)
{
    int t = blockIdx.x;
    const float* xr = x + (size_t)t * D;
    float s = 0.f, s2 = 0.f;
    for (int i = threadIdx.x; i < D; i += 256) {
        float v = xr[i];
        s += v; s2 += v * v;
    }
    float tot = blockReduceSum(s);
    float tot2 = blockReduceSum(s2);
    float mean = tot * (1.f / D);
    float var = tot2 * (1.f / D) - mean * mean;
    float rstd = rsqrtf(var + LN_EPS);
    float* orow = out + (size_t)t * D;
    for (int i = threadIdx.x; i < D; i += 256) {
        orow[i] = (xr[i] - mean) * rstd * g[i] + b[i];
    }
}

// ---------------- TF32 tensor-core GEMM NT ----------------
// C[m,n] = scale*sum_k A[m,k]*B[n,k] (+bias)(gelu)(+res)
// BM=128, BN=128, BK=32, 256 threads (8 warps, 2m x 4n), warp tile 64x32.
template<bool GELU, bool HASBIAS, bool HASRES>
__global__ __launch_bounds__(256) void k_mm_nt(
    const float* __restrict__ A, int lda, long long aHead,
    const float* __restrict__ B, int ldb, long long bHead,
    float* __restrict__ C, int ldc, long long cHead,
    int K, float scale,
    const float* __restrict__ bias,
    const float* __restrict__ res, int ldres,
    int causal)
{
    int m0 = blockIdx.y * 128, n0 = blockIdx.x * 128;
    if (causal && n0 > m0) return;
    A += (long long)blockIdx.z * aHead + (long long)m0 * lda;
    B += (long long)blockIdx.z * bHead + (long long)n0 * ldb;
    C += (long long)blockIdx.z * cHead;

    __shared__ uint32_t As[128][36];
    __shared__ uint32_t Bs[128][36];

    int tid = threadIdx.x, lane = tid & 31, warp = tid >> 5;
    int wm = (warp & 1) * 64, wn = (warp >> 1) * 32;

    float acc[4][4][4] = {};

    int lr = tid >> 3;          // 0..31
    int lc = (tid & 7) * 4;     // 0..28

    for (int k0 = 0; k0 < K; k0 += 32) {
        #pragma unroll
        for (int p = 0; p < 4; p++) {
            int row = p * 32 + lr;
            float4 av = *(const float4*)(A + (long long)row * lda + k0 + lc);
            uint4 ua = {f2tf(av.x), f2tf(av.y), f2tf(av.z), f2tf(av.w)};
            *(uint4*)&As[row][lc] = ua;
            float4 bv = *(const float4*)(B + (long long)row * ldb + k0 + lc);
            uint4 ub = {f2tf(bv.x), f2tf(bv.y), f2tf(bv.z), f2tf(bv.w)};
            *(uint4*)&Bs[row][lc] = ub;
        }
        __syncthreads();
        #pragma unroll
        for (int ks = 0; ks < 4; ks++) {
            int kb = ks * 8 + (lane & 3);
            uint32_t af[4][4], bf[4][2];
            #pragma unroll
            for (int mf = 0; mf < 4; mf++) {
                int r = wm + mf * 16 + (lane >> 2);
                af[mf][0] = As[r][kb];
                af[mf][1] = As[r + 8][kb];
                af[mf][2] = As[r][kb + 4];
                af[mf][3] = As[r + 8][kb + 4];
            }
            #pragma unroll
            for (int nf = 0; nf < 4; nf++) {
                int r = wn + nf * 8 + (lane >> 2);
                bf[nf][0] = Bs[r][kb];
                bf[nf][1] = Bs[r][kb + 4];
            }
            #pragma unroll
            for (int mf = 0; mf < 4; mf++)
                #pragma unroll
                for (int nf = 0; nf < 4; nf++)
                    mma_tf32(acc[mf][nf], af[mf], bf[nf]);
        }
        __syncthreads();
    }

    #pragma unroll
    for (int mf = 0; mf < 4; mf++) {
        int row = m0 + wm + mf * 16 + (lane >> 2);
        #pragma unroll
        for (int nf = 0; nf < 4; nf++) {
            int col = n0 + wn + nf * 8 + 2 * (lane & 3);
            #pragma unroll
            for (int half = 0; half < 2; half++) {
                int r = row + half * 8;
                float v0 = acc[mf][nf][half * 2 + 0] * scale;
                float v1 = acc[mf][nf][half * 2 + 1] * scale;
                if (HASBIAS) { v0 += bias[col]; v1 += bias[col + 1]; }
                if (GELU) {
                    v0 = 0.5f * v0 * (1.f + erff(v0 * 0.70710678118654752f));
                    v1 = 0.5f * v1 * (1.f + erff(v1 * 0.70710678118654752f));
                }
                if (HASRES) {
                    v0 += res[(long long)r * ldres + col];
                    v1 += res[(long long)r * ldres + col + 1];
                }
                float2 o = {v0, v1};
                *(float2*)(C + (long long)r * ldc + col) = o;
            }
        }
    }
}

// ---------------- TF32 tensor-core GEMM NN (P @ V), N=64 ----------------
// BM=128, BN=64, BK=32, 256 threads (8 warps, 4m x 2n), warp tile 32x32.
__global__ __launch_bounds__(256) void k_mm_nn(
    const float* __restrict__ A, int lda, long long aHead,
    const float* __restrict__ B, int ldb, long long bHead,
    float* __restrict__ C, int ldc, long long cHead,
    int K, int causal)
{
    int m0 = blockIdx.y * 128;
    A += (long long)blockIdx.z * aHead + (long long)m0 * lda;
    B += (long long)blockIdx.z * bHead;
    C += (long long)blockIdx.z * cHead;

    int Keff = causal ? min(K, m0 + 128) : K;

    __shared__ uint32_t As[128][36];
    __shared__ uint32_t Bs[64][36];

    int tid = threadIdx.x, lane = tid & 31, warp = tid >> 5;
    int wm = (warp >> 1) * 32, wn = (warp & 1) * 32;

    float acc[2][4][4] = {};

    int lr = tid >> 3;           // 0..31 (A load rows)
    int lc = (tid & 7) * 4;      // 0..28 (A load cols)
    int bk = tid & 31;           // 0..31 (B load k row)
    int bn = (tid >> 5) * 4;     // 0..28 (B load n col base, 8 warps -> 0..28)

    for (int k0 = 0; k0 < Keff; k0 += 32) {
        #pragma unroll
        for (int p = 0; p < 4; p++) {
            int row = p * 32 + lr;
            float4 av = *(const float4*)(A + (long long)row * lda + k0 + lc);
            uint4 ua = {f2tf(av.x), f2tf(av.y), f2tf(av.z), f2tf(av.w)};
            *(uint4*)&As[row][lc] = ua;
        }
        // B tile: 32 k-rows x 64 n-cols, stored transposed Bs[n][k]
        #pragma unroll
        for (int p = 0; p < 2; p++) {
            int n = bn + p * 32;
            float4 bv = *(const float4*)(B + (long long)(k0 + bk) * ldb + n);
            Bs[n + 0][bk] = f2tf(bv.x);
            Bs[n + 1][bk] = f2tf(bv.y);
            Bs[n + 2][bk] = f2tf(bv.z);
            Bs[n + 3][bk] = f2tf(bv.w);
        }
        __syncthreads();
        #pragma unroll
        for (int ks = 0; ks < 4; ks++) {
            int kb = ks * 8 + (lane & 3);
            uint32_t af[2][4], bf[4][2];
            #pragma unroll
            for (int mf = 0; mf < 2; mf++) {
                int r = wm + mf * 16 + (lane >> 2);
                af[mf][0] = As[r][kb];
                af[mf][1] = As[r + 8][kb];
                af[mf][2] = As[r][kb + 4];
                af[mf][3] = As[r + 8][kb + 4];
            }
            #pragma unroll
            for (int nf = 0; nf < 4; nf++) {
                int r = wn + nf * 8 + (lane >> 2);
                bf[nf][0] = Bs[r][kb];
                bf[nf][1] = Bs[r][kb + 4];
            }
            #pragma unroll
            for (int mf = 0; mf < 2; mf++)
                #pragma unroll
                for (int nf = 0; nf < 4; nf++)
                    mma_tf32(acc[mf][nf], af[mf], bf[nf]);
        }
        __syncthreads();
    }

    #pragma unroll
    for (int mf = 0; mf < 2; mf++) {
        int row = m0 + wm + mf * 16 + (lane >> 2);
        #pragma unroll
        for (int nf = 0; nf < 4; nf++) {
            int col = wn + nf * 8 + 2 * (lane & 3);
            #pragma unroll
            for (int half = 0; half < 2; half++) {
                int r = row + half * 8;
                float2 o = {acc[mf][nf][half * 2 + 0], acc[mf][nf][half * 2 + 1]};
                *(float2*)(C + (long long)r * ldc + col) = o;
            }
        }
    }
}

// ---------------- dual softmax + sigmoid-mean ----------------
__global__ __launch_bounds__(256) void k_softmax2(const float* __restrict__ lm)
{
    __shared__ float sS[T];
    __shared__ float sG[T];
    int t = blockIdx.x, h = blockIdx.y;
    long long roff = ((long long)h * T + t) * (long long)T;
    float* Sr = g_S + roff;
    float* P2r = g_P2 + roff;
    const float* lmr = lm + roff;

    float sigsum = 0.f, m1 = -CUDART_INF_F, m2 = -CUDART_INF_F;
    for (int s = threadIdx.x; s < T; s += 256) {
        float v = Sr[s];
        float sg = 1.f / (1.f + __expf(-lmr[s]));
        sS[s] = v; sG[s] = sg;
        sigsum += sg;
        if (s <= t) {
            m1 = fmaxf(m1, v);
            m2 = fmaxf(m2, v * sg);
        }
    }
    float tot_sig = blockReduceSum(sigsum);
    if (threadIdx.x == 0) atomicAdd(&g_sigacc, (double)tot_sig);
    m1 = blockReduceMax(m1);
    m2 = blockReduceMax(m2);

    float e1s = 0.f, e2s = 0.f;
    for (int s = threadIdx.x; s <= t; s += 256) {
        e1s += __expf(sS[s] - m1);
        e2s += __expf(sS[s] * sG[s] - m2);
    }
    float sum1 = blockReduceSum(e1s);
    float sum2 = blockReduceSum(e2s);
    float r1 = 1.f / sum1, r2 = 1.f / sum2;

    int end = min(T, ((t >> 7) + 1) << 7);   // zero to next 128-boundary (AV BM=128)
    for (int s = threadIdx.x; s < end; s += 256) {
        float p1 = 0.f, p2 = 0.f;
        if (s <= t) {
            p1 = __expf(sS[s] - m1) * r1;
            p2 = __expf(sS[s] * sG[s] - m2) * r2;
        }
        Sr[s] = p1;
        P2r[s] = p2;
    }
}

__global__ void k_zero_acc() { g_sigacc = 0.0; }

__global__ void k_write_sp(float* out, int out_size)
{
    const long long TD = (long long)T * D;
    if (out_size > TD) {
        double mean = g_sigacc / ((double)H * (double)T * (double)T);
        out[TD] = (float)(SPARSITY_LAMBDA * mean);
    }
}

// ---------------- launch ----------------
extern "C" void kernel_launch(void* const* d_in, const int* in_sizes, int n_in,
                              void* d_out, int out_size)
{
    const float* x      = (const float*)d_in[0];
    const float* W_qkv  = (const float*)d_in[2];
    const float* W_out  = (const float*)d_in[3];
    const float* logm   = (const float*)d_in[4];
    const float* W_gate = (const float*)d_in[5];
    const float* b_gate = (const float*)d_in[6];
    const float* g1     = (const float*)d_in[7];
    const float* b1     = (const float*)d_in[8];
    const float* g2     = (const float*)d_in[9];
    const float* b2     = (const float*)d_in[10];
    const float* W_ff1  = (const float*)d_in[11];
    const float* b_ff1  = (const float*)d_in[12];
    const float* W_ff2  = (const float*)d_in[13];
    const float* b_ff2  = (const float*)d_in[14];
    float* out = (float*)d_out;

    float *xn, *qkv, *S, *P2, *cat, *tmp, *hbuf, *hn, *ff;
    cudaGetSymbolAddress((void**)&xn,   g_xn);
    cudaGetSymbolAddress((void**)&qkv,  g_qkv);
    cudaGetSymbolAddress((void**)&S,    g_S);
    cudaGetSymbolAddress((void**)&P2,   g_P2);
    cudaGetSymbolAddress((void**)&cat,  g_cat);
    cudaGetSymbolAddress((void**)&tmp,  g_tmp);
    cudaGetSymbolAddress((void**)&hbuf, g_h);
    cudaGetSymbolAddress((void**)&hn,   g_hn);
    cudaGetSymbolAddress((void**)&ff,   g_ff);

    const long long TT = (long long)T * T;

    k_zero_acc<<<1, 1>>>();

    // ln1
    k_layernorm<<<T, 256>>>(x, g1, b1, xn);

    // qkv = xn @ W_qkv^T   [2048 x 3072]
    k_mm_nt<false, false, false><<<dim3(D3 / 128, T / 128, 1), 256>>>(
        xn, D, 0, W_qkv, D, 0, qkv, D3, 0, D, 1.f, nullptr, nullptr, 0, 0);

    // scores: S = Q K^T / 8 per head (block-causal skip)
    k_mm_nt<false, false, false><<<dim3(T / 128, T / 128, H), 256>>>(
        qkv, D3, DH, qkv + D, D3, DH, S, T, TT, DH, 0.125f, nullptr, nullptr, 0, 1);

    // dual softmax + sigmoid mean
    k_softmax2<<<dim3(T, H), 256>>>(logm);

    // out_txt = P_txt @ V
    k_mm_nn<<<dim3(1, T / 128, H), 256>>>(
        S, T, TT, qkv + 2 * D, D3, DH, cat, D2, DH, T, 1);
    // out_cau = P_cau @ V
    k_mm_nn<<<dim3(1, T / 128, H), 256>>>(
        P2, T, TT, qkv + 2 * D, D3, DH, cat + D, D2, DH, T, 1);

    // tmp = cat @ W_gate^T + b_gate
    k_mm_nt<false, true, false><<<dim3(D / 128, T / 128, 1), 256>>>(
        cat, D2, 0, W_gate, D2, 0, tmp, D, 0, D2, 1.f, b_gate, nullptr, 0, 0);

    // h = x + tmp @ W_out^T
    k_mm_nt<false, false, true><<<dim3(D / 128, T / 128, 1), 256>>>(
        tmp, D, 0, W_out, D, 0, hbuf, D, 0, D, 1.f, nullptr, x, D, 0);

    // ln2
    k_layernorm<<<T, 256>>>(hbuf, g2, b2, hn);

    // ff = gelu(hn @ W_ff1^T + b_ff1)
    k_mm_nt<true, true, false><<<dim3(DFF / 128, T / 128, 1), 256>>>(
        hn, D, 0, W_ff1, D, 0, ff, DFF, 0, D, 1.f, b_ff1, nullptr, 0, 0);

    // out = h + ff @ W_ff2^T + b_ff2
    k_mm_nt<false, true, true><<<dim3(D / 128, T / 128, 1), 256>>>(
        ff, DFF, 0, W_ff2, DFF, 0, out, D, 0, DFF, 1.f, b_ff2, hbuf, D, 0);

    k_write_sp<<<1, 1>>>(out, out_size);
}

// round 4
// speedup vs baseline: 2.9384x; 1.3320x over previous
#include <cuda_runtime.h>
#include <cuda_bf16.h>
#include <math_constants.h>
#include <cstdint>

// Problem constants
#define T 2048
#define D 1024
#define H 16
#define DH 64
#define D3 3072
#define D2 2048
#define DFF 4096
#define LN_EPS 1e-5f
#define SPARSITY_LAMBDA 0.0005f

// ---------------- scratch ----------------
__device__ float g_xn[(size_t)T * D];
__device__ float g_qkv[(size_t)T * D3];
__device__ float g_S[(size_t)H * T * T];
__device__ float g_P2[(size_t)H * T * T];
__device__ float g_cat[(size_t)T * D2];
__device__ float g_tmp[(size_t)T * D];
__device__ float g_h[(size_t)T * D];
__device__ float g_hn[(size_t)T * D];
__device__ float g_ff[(size_t)T * DFF];
__device__ double g_sigacc;

// ---------------- helpers ----------------
__device__ __forceinline__ uint32_t f2tf(float f) {
    uint32_t u;
    asm("cvt.rna.tf32.f32 %0, %1;" : "=r"(u) : "f"(f));
    return u;
}

__device__ __forceinline__ void mma_tf32(float (&d)[4], const uint32_t (&a)[4], const uint32_t (&b)[2]) {
    asm volatile(
        "mma.sync.aligned.m16n8k8.row.col.f32.tf32.tf32.f32 "
        "{%0,%1,%2,%3}, {%4,%5,%6,%7}, {%8,%9}, {%0,%1,%2,%3};\n"
        : "+f"(d[0]), "+f"(d[1]), "+f"(d[2]), "+f"(d[3])
        : "r"(a[0]), "r"(a[1]), "r"(a[2]), "r"(a[3]), "r"(b[0]), "r"(b[1]));
}

__device__ __forceinline__ void cp16(float* sdst, const float* gsrc) {
    uint32_t s = (uint32_t)__cvta_generic_to_shared(sdst);
    asm volatile("cp.async.cg.shared.global [%0], [%1], 16;" :: "r"(s), "l"(gsrc));
}
__device__ __forceinline__ void cp_commit() { asm volatile("cp.async.commit_group;"); }
template<int N> __device__ __forceinline__ void cp_wait() {
    asm volatile("cp.async.wait_group %0;" :: "n"(N));
}

__device__ __forceinline__ float blockReduceSum(float v) {
    __shared__ float red[32];
    int lane = threadIdx.x & 31, wid = threadIdx.x >> 5;
    #pragma unroll
    for (int o = 16; o > 0; o >>= 1) v += __shfl_xor_sync(0xffffffff, v, o);
    __syncthreads();
    if (lane == 0) red[wid] = v;
    __syncthreads();
    int nw = (blockDim.x + 31) >> 5;
    float r = (threadIdx.x < nw) ? red[threadIdx.x] : 0.f;
    if (wid == 0) {
        #pragma unroll
        for (int o = 16; o > 0; o >>= 1) r += __shfl_xor_sync(0xffffffff, r, o);
        if (lane == 0) red[0] = r;
    }
    __syncthreads();
    return red[0];
}

__device__ __forceinline__ float blockReduceMax(float v) {
    __shared__ float red[32];
    int lane = threadIdx.x & 31, wid = threadIdx.x >> 5;
    #pragma unroll
    for (int o = 16; o > 0; o >>= 1) v = fmaxf(v, __shfl_xor_sync(0xffffffff, v, o));
    __syncthreads();
    if (lane == 0) red[wid] = v;
    __syncthreads();
    int nw = (blockDim.x + 31) >> 5;
    float r = (threadIdx.x < nw) ? red[threadIdx.x] : -CUDART_INF_F;
    if (wid == 0) {
        #pragma unroll
        for (int o = 16; o > 0; o >>= 1) r = fmaxf(r, __shfl_xor_sync(0xffffffff, r, o));
        if (lane == 0) red[0] = r;
    }
    __syncthreads();
    return red[0];
}

// ---------------- layernorm ----------------
__global__ __launch_bounds__(256) void k_layernorm(
    const float* __restrict__ x, const float* __restrict__ g,
    const float* __restrict__ b, float* __restrict__ out)
{
    int t = blockIdx.x;
    const float* xr = x + (size_t)t * D;
    float s = 0.f, s2 = 0.f;
    for (int i = threadIdx.x; i < D; i += 256) {
        float v = xr[i];
        s += v; s2 += v * v;
    }
    float tot = blockReduceSum(s);
    float tot2 = blockReduceSum(s2);
    float mean = tot * (1.f / D);
    float var = tot2 * (1.f / D) - mean * mean;
    float rstd = rsqrtf(var + LN_EPS);
    float* orow = out + (size_t)t * D;
    for (int i = threadIdx.x; i < D; i += 256) {
        orow[i] = (xr[i] - mean) * rstd * g[i] + b[i];
    }
}

// ---------------- TF32 GEMM NT, cp.async double-buffered ----------------
// C[m,n] = scale*sum_k A[m,k]*B[n,k] (+bias)(gelu)(+res)
// BM=BN=128, BK=32, 256 threads (8 warps 2m x 4n), warp tile 64x32.
#define NT_STAGE 4608   // 128*36 floats
template<bool GELU, bool HASBIAS, bool HASRES>
__global__ __launch_bounds__(256) void k_mm_nt(
    const float* __restrict__ A, int lda, long long aHead,
    const float* __restrict__ B, int ldb, long long bHead,
    float* __restrict__ C, int ldc, long long cHead,
    int K, float scale,
    const float* __restrict__ bias,
    const float* __restrict__ res, int ldres,
    int causal)
{
    int m0 = blockIdx.y * 128, n0 = blockIdx.x * 128;
    if (causal && n0 > m0) return;
    A += (long long)blockIdx.z * aHead + (long long)m0 * lda;
    B += (long long)blockIdx.z * bHead + (long long)n0 * ldb;
    C += (long long)blockIdx.z * cHead;

    extern __shared__ float sm_nt[];
    float* Abuf = sm_nt;                // [2][128][36]
    float* Bbuf = sm_nt + 2 * NT_STAGE; // [2][128][36]

    int tid = threadIdx.x, lane = tid & 31, warp = tid >> 5;
    int wm = (warp & 1) * 64, wn = (warp >> 1) * 32;
    int lr = tid >> 3, lc = (tid & 7) * 4;

    float acc[4][4][4] = {};

    auto load = [&](int st, int k0) {
        float* As_ = Abuf + st * NT_STAGE;
        float* Bs_ = Bbuf + st * NT_STAGE;
        #pragma unroll
        for (int p = 0; p < 4; p++) {
            int row = p * 32 + lr;
            cp16(As_ + row * 36 + lc, A + (long long)row * lda + k0 + lc);
            cp16(Bs_ + row * 36 + lc, B + (long long)row * ldb + k0 + lc);
        }
    };

    load(0, 0); cp_commit();

    int st = 0;
    for (int k0 = 0; k0 < K; k0 += 32, st ^= 1) {
        bool more = (k0 + 32 < K);
        if (more) { load(st ^ 1, k0 + 32); cp_commit(); }
        if (more) cp_wait<1>(); else cp_wait<0>();
        __syncthreads();
        const float* As_ = Abuf + st * NT_STAGE;
        const float* Bs_ = Bbuf + st * NT_STAGE;
        #pragma unroll
        for (int ks = 0; ks < 4; ks++) {
            int kb = ks * 8 + (lane & 3);
            uint32_t af[4][4], bf[4][2];
            #pragma unroll
            for (int mf = 0; mf < 4; mf++) {
                int r = wm + mf * 16 + (lane >> 2);
                af[mf][0] = f2tf(As_[r * 36 + kb]);
                af[mf][1] = f2tf(As_[(r + 8) * 36 + kb]);
                af[mf][2] = f2tf(As_[r * 36 + kb + 4]);
                af[mf][3] = f2tf(As_[(r + 8) * 36 + kb + 4]);
            }
            #pragma unroll
            for (int nf = 0; nf < 4; nf++) {
                int r = wn + nf * 8 + (lane >> 2);
                bf[nf][0] = f2tf(Bs_[r * 36 + kb]);
                bf[nf][1] = f2tf(Bs_[r * 36 + kb + 4]);
            }
            #pragma unroll
            for (int mf = 0; mf < 4; mf++)
                #pragma unroll
                for (int nf = 0; nf < 4; nf++)
                    mma_tf32(acc[mf][nf], af[mf], bf[nf]);
        }
        __syncthreads();
    }

    #pragma unroll
    for (int mf = 0; mf < 4; mf++) {
        int row = m0 + wm + mf * 16 + (lane >> 2);
        #pragma unroll
        for (int nf = 0; nf < 4; nf++) {
            int col = n0 + wn + nf * 8 + 2 * (lane & 3);
            #pragma unroll
            for (int half = 0; half < 2; half++) {
                int r = row + half * 8;
                float v0 = acc[mf][nf][half * 2 + 0] * scale;
                float v1 = acc[mf][nf][half * 2 + 1] * scale;
                if (HASBIAS) { v0 += bias[col]; v1 += bias[col + 1]; }
                if (GELU) {
                    v0 = 0.5f * v0 * (1.f + erff(v0 * 0.70710678118654752f));
                    v1 = 0.5f * v1 * (1.f + erff(v1 * 0.70710678118654752f));
                }
                if (HASRES) {
                    v0 += res[(long long)r * ldres + col];
                    v1 += res[(long long)r * ldres + col + 1];
                }
                float2 o = {v0, v1};
                *(float2*)(C + (long long)r * ldc + col) = o;
            }
        }
    }
}

// ---------------- TF32 GEMM NN (P @ V), N=64, cp.async double-buffered ----------------
// BM=128, BN=64, BK=32. A tile [128][36]; B tile natural [32][72] (pad 8).
#define NN_ASTAGE 4608   // 128*36
#define NN_BSTAGE 2304   // 32*72
__global__ __launch_bounds__(256) void k_mm_nn(
    const float* __restrict__ A, int lda, long long aHead,
    const float* __restrict__ B, int ldb, long long bHead,
    float* __restrict__ C, int ldc, long long cHead,
    int K, int causal)
{
    int m0 = blockIdx.y * 128;
    A += (long long)blockIdx.z * aHead + (long long)m0 * lda;
    B += (long long)blockIdx.z * bHead;
    C += (long long)blockIdx.z * cHead;

    int Keff = causal ? min(K, m0 + 128) : K;

    extern __shared__ float sm_nn[];
    float* Abuf = sm_nn;                  // [2][128][36]
    float* Bbuf = sm_nn + 2 * NN_ASTAGE;  // [2][32][72]

    int tid = threadIdx.x, lane = tid & 31, warp = tid >> 5;
    int wm = (warp >> 1) * 32, wn = (warp & 1) * 32;
    int lr = tid >> 3, lc = (tid & 7) * 4;

    float acc[2][4][4] = {};

    auto load = [&](int st, int k0) {
        float* As_ = Abuf + st * NN_ASTAGE;
        float* Bs_ = Bbuf + st * NN_BSTAGE;
        #pragma unroll
        for (int p = 0; p < 4; p++) {
            int row = p * 32 + lr;
            cp16(As_ + row * 36 + lc, A + (long long)row * lda + k0 + lc);
        }
        // B tile 32 rows x 64 cols: 256 threads x 2 cp16 = 8192 B (full coverage)
        int kr = tid >> 3;           // 0..31
        int c4 = (tid & 7) * 4;      // 0..28
        cp16(Bs_ + kr * 72 + c4,      B + (long long)(k0 + kr) * ldb + c4);
        cp16(Bs_ + kr * 72 + c4 + 32, B + (long long)(k0 + kr) * ldb + c4 + 32);
    };

    load(0, 0); cp_commit();

    int st = 0;
    for (int k0 = 0; k0 < Keff; k0 += 32, st ^= 1) {
        bool more = (k0 + 32 < Keff);
        if (more) { load(st ^ 1, k0 + 32); cp_commit(); }
        if (more) cp_wait<1>(); else cp_wait<0>();
        __syncthreads();
        const float* As_ = Abuf + st * NN_ASTAGE;
        const float* Bs_ = Bbuf + st * NN_BSTAGE;
        #pragma unroll
        for (int ks = 0; ks < 4; ks++) {
            int kb = ks * 8 + (lane & 3);
            uint32_t af[2][4], bf[4][2];
            #pragma unroll
            for (int mf = 0; mf < 2; mf++) {
                int r = wm + mf * 16 + (lane >> 2);
                af[mf][0] = f2tf(As_[r * 36 + kb]);
                af[mf][1] = f2tf(As_[(r + 8) * 36 + kb]);
                af[mf][2] = f2tf(As_[r * 36 + kb + 4]);
                af[mf][3] = f2tf(As_[(r + 8) * 36 + kb + 4]);
            }
            #pragma unroll
            for (int nf = 0; nf < 4; nf++) {
                int n = wn + nf * 8 + (lane >> 2);
                bf[nf][0] = f2tf(Bs_[kb * 72 + n]);
                bf[nf][1] = f2tf(Bs_[(kb + 4) * 72 + n]);
            }
            #pragma unroll
            for (int mf = 0; mf < 2; mf++)
                #pragma unroll
                for (int nf = 0; nf < 4; nf++)
                    mma_tf32(acc[mf][nf], af[mf], bf[nf]);
        }
        __syncthreads();
    }

    #pragma unroll
    for (int mf = 0; mf < 2; mf++) {
        int row = m0 + wm + mf * 16 + (lane >> 2);
        #pragma unroll
        for (int nf = 0; nf < 4; nf++) {
            int col = wn + nf * 8 + 2 * (lane & 3);
            #pragma unroll
            for (int half = 0; half < 2; half++) {
                int r = row + half * 8;
                float2 o = {acc[mf][nf][half * 2 + 0], acc[mf][nf][half * 2 + 1]};
                *(float2*)(C + (long long)r * ldc + col) = o;
            }
        }
    }
}

// ---------------- dual softmax + sigmoid-mean ----------------
__global__ __launch_bounds__(256) void k_softmax2(const float* __restrict__ lm)
{
    __shared__ float sS[T];
    __shared__ float sG[T];
    int t = blockIdx.x, h = blockIdx.y;
    long long roff = ((long long)h * T + t) * (long long)T;
    float* Sr = g_S + roff;
    float* P2r = g_P2 + roff;
    const float* lmr = lm + roff;

    float sigsum = 0.f;
    for (int s = threadIdx.x; s < T; s += 256) {
        float sg = 1.f / (1.f + __expf(-lmr[s]));
        sG[s] = sg;
        sigsum += sg;
    }
    float m1 = -CUDART_INF_F, m2 = -CUDART_INF_F;
    for (int s = threadIdx.x; s <= t; s += 256) {
        float v = Sr[s];
        sS[s] = v;
        m1 = fmaxf(m1, v);
        m2 = fmaxf(m2, v * sG[s]);
    }
    float tot_sig = blockReduceSum(sigsum);
    if (threadIdx.x == 0) atomicAdd(&g_sigacc, (double)tot_sig);
    m1 = blockReduceMax(m1);
    m2 = blockReduceMax(m2);

    float e1s = 0.f, e2s = 0.f;
    for (int s = threadIdx.x; s <= t; s += 256) {
        e1s += __expf(sS[s] - m1);
        e2s += __expf(sS[s] * sG[s] - m2);
    }
    float sum1 = blockReduceSum(e1s);
    float sum2 = blockReduceSum(e2s);
    float r1 = 1.f / sum1, r2 = 1.f / sum2;

    int end = min(T, ((t >> 7) + 1) << 7);   // zero up to next 128-boundary (AV BM=128)
    for (int s = threadIdx.x; s < end; s += 256) {
        float p1 = 0.f, p2 = 0.f;
        if (s <= t) {
            p1 = __expf(sS[s] - m1) * r1;
            p2 = __expf(sS[s] * sG[s] - m2) * r2;
        }
        Sr[s] = p1;
        P2r[s] = p2;
    }
}

__global__ void k_zero_acc() { g_sigacc = 0.0; }

__global__ void k_write_sp(float* out, int out_size)
{
    const long long TD = (long long)T * D;
    if (out_size > TD) {
        double mean = g_sigacc / ((double)H * (double)T * (double)T);
        out[TD] = (float)(SPARSITY_LAMBDA * mean);
    }
}

// ---------------- launch ----------------
#define NT_SMEM (4 * NT_STAGE * sizeof(float))                    // 73728
#define NN_SMEM ((2 * NN_ASTAGE + 2 * NN_BSTAGE) * sizeof(float)) // 55296

extern "C" void kernel_launch(void* const* d_in, const int* in_sizes, int n_in,
                              void* d_out, int out_size)
{
    const float* x      = (const float*)d_in[0];
    const float* W_qkv  = (const float*)d_in[2];
    const float* W_out  = (const float*)d_in[3];
    const float* logm   = (const float*)d_in[4];
    const float* W_gate = (const float*)d_in[5];
    const float* b_gate = (const float*)d_in[6];
    const float* g1     = (const float*)d_in[7];
    const float* b1     = (const float*)d_in[8];
    const float* g2     = (const float*)d_in[9];
    const float* b2     = (const float*)d_in[10];
    const float* W_ff1  = (const float*)d_in[11];
    const float* b_ff1  = (const float*)d_in[12];
    const float* W_ff2  = (const float*)d_in[13];
    const float* b_ff2  = (const float*)d_in[14];
    float* out = (float*)d_out;

    float *xn, *qkv, *S, *P2, *cat, *tmp, *hbuf, *hn, *ff;
    cudaGetSymbolAddress((void**)&xn,   g_xn);
    cudaGetSymbolAddress((void**)&qkv,  g_qkv);
    cudaGetSymbolAddress((void**)&S,    g_S);
    cudaGetSymbolAddress((void**)&P2,   g_P2);
    cudaGetSymbolAddress((void**)&cat,  g_cat);
    cudaGetSymbolAddress((void**)&tmp,  g_tmp);
    cudaGetSymbolAddress((void**)&hbuf, g_h);
    cudaGetSymbolAddress((void**)&hn,   g_hn);
    cudaGetSymbolAddress((void**)&ff,   g_ff);

    cudaFuncSetAttribute(k_mm_nt<false, false, false>, cudaFuncAttributeMaxDynamicSharedMemorySize, NT_SMEM);
    cudaFuncSetAttribute(k_mm_nt<false, true,  false>, cudaFuncAttributeMaxDynamicSharedMemorySize, NT_SMEM);
    cudaFuncSetAttribute(k_mm_nt<false, false, true >, cudaFuncAttributeMaxDynamicSharedMemorySize, NT_SMEM);
    cudaFuncSetAttribute(k_mm_nt<false, true,  true >, cudaFuncAttributeMaxDynamicSharedMemorySize, NT_SMEM);
    cudaFuncSetAttribute(k_mm_nt<true,  true,  false>, cudaFuncAttributeMaxDynamicSharedMemorySize, NT_SMEM);
    cudaFuncSetAttribute(k_mm_nn, cudaFuncAttributeMaxDynamicSharedMemorySize, NN_SMEM);

    const long long TT = (long long)T * T;

    k_zero_acc<<<1, 1>>>();

    // ln1
    k_layernorm<<<T, 256>>>(x, g1, b1, xn);

    // qkv = xn @ W_qkv^T
    k_mm_nt<false, false, false><<<dim3(D3 / 128, T / 128, 1), 256, NT_SMEM>>>(
        xn, D, 0, W_qkv, D, 0, qkv, D3, 0, D, 1.f, nullptr, nullptr, 0, 0);

    // scores: S = Q K^T / 8 per head (block-causal skip)
    k_mm_nt<false, false, false><<<dim3(T / 128, T / 128, H), 256, NT_SMEM>>>(
        qkv, D3, DH, qkv + D, D3, DH, S, T, TT, DH, 0.125f, nullptr, nullptr, 0, 1);

    // dual softmax + sigmoid mean
    k_softmax2<<<dim3(T, H), 256>>>(logm);

    // out_txt = P_txt @ V ; out_cau = P_cau @ V
    k_mm_nn<<<dim3(1, T / 128, H), 256, NN_SMEM>>>(
        S, T, TT, qkv + 2 * D, D3, DH, cat, D2, DH, T, 1);
    k_mm_nn<<<dim3(1, T / 128, H), 256, NN_SMEM>>>(
        P2, T, TT, qkv + 2 * D, D3, DH, cat + D, D2, DH, T, 1);

    // tmp = cat @ W_gate^T + b_gate
    k_mm_nt<false, true, false><<<dim3(D / 128, T / 128, 1), 256, NT_SMEM>>>(
        cat, D2, 0, W_gate, D2, 0, tmp, D, 0, D2, 1.f, b_gate, nullptr, 0, 0);

    // h = x + tmp @ W_out^T
    k_mm_nt<false, false, true><<<dim3(D / 128, T / 128, 1), 256, NT_SMEM>>>(
        tmp, D, 0, W_out, D, 0, hbuf, D, 0, D, 1.f, nullptr, x, D, 0);

    // ln2
    k_layernorm<<<T, 256>>>(hbuf, g2, b2, hn);

    // ff = gelu(hn @ W_ff1^T + b_ff1)
    k_mm_nt<true, true, false><<<dim3(DFF / 128, T / 128, 1), 256, NT_SMEM>>>(
        hn, D, 0, W_ff1, D, 0, ff, DFF, 0, D, 1.f, b_ff1, nullptr, 0, 0);

    // out = h + ff @ W_ff2^T + b_ff2
    k_mm_nt<false, true, true><<<dim3(D / 128, T / 128, 1), 256, NT_SMEM>>>(
        ff, DFF, 0, W_ff2, DFF, 0, out, D, 0, DFF, 1.f, b_ff2, hbuf, D, 0);

    k_write_sp<<<1, 1>>>(out, out_size);
}

// round 5
// speedup vs baseline: 3.0277x; 1.0304x over previous
#include <cuda_runtime.h>
#include <cuda_bf16.h>
#include <math_constants.h>
#include <cstdint>

#define T 2048
#define D 1024
#define H 16
#define DH 64
#define D3 3072
#define D2 2048
#define DFF 4096
#define LN_EPS 1e-5f
#define SPARSITY_LAMBDA 0.0005f

// ---------------- scratch ----------------
__device__ float g_xn[(size_t)T * D];
__device__ float g_qkv[(size_t)T * D3];
__device__ float g_cat[(size_t)T * D2];
__device__ float g_tmp[(size_t)T * D];
__device__ float g_h[(size_t)T * D];
__device__ float g_hn[(size_t)T * D];
__device__ float g_ff[(size_t)T * DFF];
__device__ double g_sigacc;

// ---------------- helpers ----------------
__device__ __forceinline__ uint32_t f2tf(float f) {
    uint32_t u;
    asm("cvt.rna.tf32.f32 %0, %1;" : "=r"(u) : "f"(f));
    return u;
}

__device__ __forceinline__ void mma_tf32(float (&d)[4], const uint32_t (&a)[4], const uint32_t (&b)[2]) {
    asm volatile(
        "mma.sync.aligned.m16n8k8.row.col.f32.tf32.tf32.f32 "
        "{%0,%1,%2,%3}, {%4,%5,%6,%7}, {%8,%9}, {%0,%1,%2,%3};\n"
        : "+f"(d[0]), "+f"(d[1]), "+f"(d[2]), "+f"(d[3])
        : "r"(a[0]), "r"(a[1]), "r"(a[2]), "r"(a[3]), "r"(b[0]), "r"(b[1]));
}

__device__ __forceinline__ void cp16(float* sdst, const float* gsrc) {
    uint32_t s = (uint32_t)__cvta_generic_to_shared(sdst);
    asm volatile("cp.async.cg.shared.global [%0], [%1], 16;" :: "r"(s), "l"(gsrc));
}
__device__ __forceinline__ void cp_commit() { asm volatile("cp.async.commit_group;"); }
template<int N> __device__ __forceinline__ void cp_wait() {
    asm volatile("cp.async.wait_group %0;" :: "n"(N));
}

__device__ __forceinline__ float sigf(float x) { return 1.f / (1.f + __expf(-x)); }

__device__ __forceinline__ float blockReduceSum(float v) {
    __shared__ float red[32];
    int lane = threadIdx.x & 31, wid = threadIdx.x >> 5;
    #pragma unroll
    for (int o = 16; o > 0; o >>= 1) v += __shfl_xor_sync(0xffffffff, v, o);
    __syncthreads();
    if (lane == 0) red[wid] = v;
    __syncthreads();
    int nw = (blockDim.x + 31) >> 5;
    float r = (threadIdx.x < nw) ? red[threadIdx.x] : 0.f;
    if (wid == 0) {
        #pragma unroll
        for (int o = 16; o > 0; o >>= 1) r += __shfl_xor_sync(0xffffffff, r, o);
        if (lane == 0) red[0] = r;
    }
    __syncthreads();
    return red[0];
}

// ---------------- layernorm ----------------
__global__ __launch_bounds__(256) void k_layernorm(
    const float* __restrict__ x, const float* __restrict__ g,
    const float* __restrict__ b, float* __restrict__ out)
{
    int t = blockIdx.x;
    const float* xr = x + (size_t)t * D;
    float s = 0.f, s2 = 0.f;
    for (int i = threadIdx.x; i < D; i += 256) {
        float v = xr[i];
        s += v; s2 += v * v;
    }
    float tot = blockReduceSum(s);
    float tot2 = blockReduceSum(s2);
    float mean = tot * (1.f / D);
    float var = tot2 * (1.f / D) - mean * mean;
    float rstd = rsqrtf(var + LN_EPS);
    float* orow = out + (size_t)t * D;
    for (int i = threadIdx.x; i < D; i += 256) {
        orow[i] = (xr[i] - mean) * rstd * g[i] + b[i];
    }
}

// ---------------- TF32 GEMM NT, cp.async 3-stage ----------------
// C[m,n] = scale*sum_k A[m,k]*B[n,k] (+bias)(gelu)(+res)(round-to-tf32)
#define NT_STAGE 4608   // 128*36 floats
template<bool GELU, bool HASBIAS, bool HASRES, bool ROUND>
__global__ __launch_bounds__(256) void k_mm_nt(
    const float* __restrict__ A, int lda,
    const float* __restrict__ B, int ldb,
    float* __restrict__ C, int ldc,
    int K, float scale,
    const float* __restrict__ bias,
    const float* __restrict__ res, int ldres)
{
    int m0 = blockIdx.y * 128, n0 = blockIdx.x * 128;
    A += (long long)m0 * lda;
    B += (long long)n0 * ldb;

    extern __shared__ float sm_nt[];
    float* Abuf = sm_nt;                // [3][128][36]
    float* Bbuf = sm_nt + 3 * NT_STAGE; // [3][128][36]

    int tid = threadIdx.x, lane = tid & 31, warp = tid >> 5;
    int wm = (warp & 1) * 64, wn = (warp >> 1) * 32;
    int lr = tid >> 3, lc = (tid & 7) * 4;

    float acc[4][4][4] = {};

    auto load = [&](int st, int k0) {
        float* As_ = Abuf + st * NT_STAGE;
        float* Bs_ = Bbuf + st * NT_STAGE;
        #pragma unroll
        for (int p = 0; p < 4; p++) {
            int row = p * 32 + lr;
            cp16(As_ + row * 36 + lc, A + (long long)row * lda + k0 + lc);
            cp16(Bs_ + row * 36 + lc, B + (long long)row * ldb + k0 + lc);
        }
    };

    int nk = K / 32;
    load(0, 0); cp_commit();
    load(1, 32); cp_commit();

    for (int i = 0; i < nk; i++) {
        if (i + 1 < nk) cp_wait<1>(); else cp_wait<0>();
        __syncthreads();
        if (i + 2 < nk) { load((i + 2) % 3, (i + 2) * 32); cp_commit(); }

        const float* As_ = Abuf + (i % 3) * NT_STAGE;
        const float* Bs_ = Bbuf + (i % 3) * NT_STAGE;
        #pragma unroll
        for (int ks = 0; ks < 4; ks++) {
            int kb = ks * 8 + (lane & 3);
            uint32_t af[4][4], bf[4][2];
            #pragma unroll
            for (int mf = 0; mf < 4; mf++) {
                int r = wm + mf * 16 + (lane >> 2);
                af[mf][0] = f2tf(As_[r * 36 + kb]);
                af[mf][1] = f2tf(As_[(r + 8) * 36 + kb]);
                af[mf][2] = f2tf(As_[r * 36 + kb + 4]);
                af[mf][3] = f2tf(As_[(r + 8) * 36 + kb + 4]);
            }
            #pragma unroll
            for (int nf = 0; nf < 4; nf++) {
                int r = wn + nf * 8 + (lane >> 2);
                bf[nf][0] = f2tf(Bs_[r * 36 + kb]);
                bf[nf][1] = f2tf(Bs_[r * 36 + kb + 4]);
            }
            #pragma unroll
            for (int mf = 0; mf < 4; mf++)
                #pragma unroll
                for (int nf = 0; nf < 4; nf++)
                    mma_tf32(acc[mf][nf], af[mf], bf[nf]);
        }
    }

    #pragma unroll
    for (int mf = 0; mf < 4; mf++) {
        int row = m0 + wm + mf * 16 + (lane >> 2);
        #pragma unroll
        for (int nf = 0; nf < 4; nf++) {
            int col = n0 + wn + nf * 8 + 2 * (lane & 3);
            #pragma unroll
            for (int half = 0; half < 2; half++) {
                int r = row + half * 8;
                float v0 = acc[mf][nf][half * 2 + 0] * scale;
                float v1 = acc[mf][nf][half * 2 + 1] * scale;
                if (HASBIAS) { v0 += bias[col]; v1 += bias[col + 1]; }
                if (GELU) {
                    v0 = 0.5f * v0 * (1.f + erff(v0 * 0.70710678118654752f));
                    v1 = 0.5f * v1 * (1.f + erff(v1 * 0.70710678118654752f));
                }
                if (HASRES) {
                    v0 += res[(long long)r * ldres + col];
                    v1 += res[(long long)r * ldres + col + 1];
                }
                if (ROUND) {
                    v0 = __uint_as_float(f2tf(v0));
                    v1 = __uint_as_float(f2tf(v1));
                }
                float2 o = {v0, v1};
                *(float2*)(C + (long long)r * ldc + col) = o;
            }
        }
    }
}

// ---------------- fused dual-softmax flash attention ----------------
// One CTA per (head, 128 query rows). 8 warps x 16 rows. KB=64 key tiles,
// double-buffered cp.async for K/V/logm. Both branches online-softmaxed.
// qkv must be pre-rounded to tf32 (ROUND epilogue of qkv GEMM).
__global__ __launch_bounds__(256) void k_flash(
    const float* __restrict__ qkv, const float* __restrict__ logm,
    float* __restrict__ cat)
{
    extern __shared__ float sm[];
    float* sQ = sm;             // [128][68]
    float* sK = sm + 8704;      // [2][64][68]
    float* sV = sm + 17408;     // [2][64][72]
    float* sM = sm + 26624;     // [2][128][68]

    int bid = blockIdx.x;
    int qi = 15 - (bid >> 4);   // heavy blocks first
    int h  = bid & 15;
    int q0 = qi * 128;
    int nkb = 2 * (qi + 1);

    int tid = threadIdx.x, lane = tid & 31, warp = tid >> 5;
    int p_ = lane >> 2, q_ = lane & 3;
    int wrow0 = warp * 16;

    // Q tile + stage-0 K/V/M loads
    #pragma unroll
    for (int i = 0; i < 8; i++) {
        int idx = tid + i * 256;
        int row = idx >> 4, c4 = (idx & 15) * 4;
        cp16(sQ + row * 68 + c4, qkv + (size_t)(q0 + row) * D3 + h * 64 + c4);
    }
    #pragma unroll
    for (int i = 0; i < 4; i++) {
        int idx = tid + i * 256;
        int row = idx >> 4, c4 = (idx & 15) * 4;
        cp16(sK + row * 68 + c4, qkv + (size_t)row * D3 + D + h * 64 + c4);
        cp16(sV + row * 72 + c4, qkv + (size_t)row * D3 + 2 * D + h * 64 + c4);
    }
    #pragma unroll
    for (int i = 0; i < 8; i++) {
        int idx = tid + i * 256;
        int row = idx >> 4, c4 = (idx & 15) * 4;
        cp16(sM + row * 68 + c4, logm + ((size_t)h * T + q0 + row) * T + c4);
    }
    cp_commit();

    float O1[8][4] = {}, O2[8][4] = {};
    float m1[2] = {-1e30f, -1e30f}, l1[2] = {0.f, 0.f};
    float m2[2] = {-1e30f, -1e30f}, l2[2] = {0.f, 0.f};
    float ssum = 0.f;

    int r0 = wrow0 + p_;
    int t0 = q0 + r0, t1 = t0 + 8;
    int srcA = (lane & ~3) | (q_ >> 1);
    int srcB = srcA + 2;
    bool odd = q_ & 1;

    for (int j = 0; j < nkb; j++) {
        int st = j & 1;
        int kb0 = j * 64;
        cp_wait<0>();
        __syncthreads();
        if (j + 1 < nkb) {
            int st2 = st ^ 1, kb2 = kb0 + 64;
            float* dK = sK + st2 * 4352;
            float* dV = sV + st2 * 4608;
            float* dM = sM + st2 * 8704;
            #pragma unroll
            for (int i = 0; i < 4; i++) {
                int idx = tid + i * 256;
                int row = idx >> 4, c4 = (idx & 15) * 4;
                cp16(dK + row * 68 + c4, qkv + (size_t)(kb2 + row) * D3 + D + h * 64 + c4);
                cp16(dV + row * 72 + c4, qkv + (size_t)(kb2 + row) * D3 + 2 * D + h * 64 + c4);
            }
            #pragma unroll
            for (int i = 0; i < 8; i++) {
                int idx = tid + i * 256;
                int row = idx >> 4, c4 = (idx & 15) * 4;
                cp16(dM + row * 68 + c4, logm + ((size_t)h * T + q0 + row) * T + kb2 + c4);
            }
            cp_commit();
        }

        const float* sK_ = sK + st * 4352;
        const float* sV_ = sV + st * 4608;
        const float* sM_ = sM + st * 8704;

        // sigmoid tile (also feeds the sparsity mean)
        float sg[8][4];
        #pragma unroll
        for (int nf = 0; nf < 8; nf++) {
            int c0 = nf * 8 + 2 * q_;
            float2 a = *(const float2*)(sM_ + r0 * 68 + c0);
            float2 b = *(const float2*)(sM_ + (r0 + 8) * 68 + c0);
            sg[nf][0] = sigf(a.x); sg[nf][1] = sigf(a.y);
            sg[nf][2] = sigf(b.x); sg[nf][3] = sigf(b.y);
            ssum += sg[nf][0] + sg[nf][1] + sg[nf][2] + sg[nf][3];
        }

        if (kb0 > q0 + wrow0 + 15) continue;   // tile fully above diagonal for this warp

        // S = Q K^T / 8
        float sc[8][4] = {};
        #pragma unroll
        for (int kc = 0; kc < 8; kc++) {
            int kb = kc * 8 + q_;
            uint32_t af[4];
            af[0] = __float_as_uint(sQ[r0 * 68 + kb]);
            af[1] = __float_as_uint(sQ[(r0 + 8) * 68 + kb]);
            af[2] = __float_as_uint(sQ[r0 * 68 + kb + 4]);
            af[3] = __float_as_uint(sQ[(r0 + 8) * 68 + kb + 4]);
            #pragma unroll
            for (int nf = 0; nf < 8; nf++) {
                uint32_t bf[2];
                bf[0] = __float_as_uint(sK_[(nf * 8 + p_) * 68 + kb]);
                bf[1] = __float_as_uint(sK_[(nf * 8 + p_) * 68 + kb + 4]);
                mma_tf32(sc[nf], af, bf);
            }
        }
        #pragma unroll
        for (int nf = 0; nf < 8; nf++) {
            sc[nf][0] *= 0.125f; sc[nf][1] *= 0.125f;
            sc[nf][2] *= 0.125f; sc[nf][3] *= 0.125f;
        }

        // ---- two online-softmax branches ----
        #pragma unroll
        for (int br = 0; br < 2; br++) {
            float* mB = br ? m2 : m1;
            float* lB = br ? l2 : l1;
            float (*OB)[4] = br ? O2 : O1;

            float v[8][4];
            float rmx0 = -1e30f, rmx1 = -1e30f;
            #pragma unroll
            for (int nf = 0; nf < 8; nf++) {
                int c0 = kb0 + nf * 8 + 2 * q_;
                float w0 = br ? sc[nf][0] * sg[nf][0] : sc[nf][0];
                float w1 = br ? sc[nf][1] * sg[nf][1] : sc[nf][1];
                float w2 = br ? sc[nf][2] * sg[nf][2] : sc[nf][2];
                float w3 = br ? sc[nf][3] * sg[nf][3] : sc[nf][3];
                v[nf][0] = (c0     <= t0) ? w0 : -1e30f;
                v[nf][1] = (c0 + 1 <= t0) ? w1 : -1e30f;
                v[nf][2] = (c0     <= t1) ? w2 : -1e30f;
                v[nf][3] = (c0 + 1 <= t1) ? w3 : -1e30f;
                rmx0 = fmaxf(rmx0, fmaxf(v[nf][0], v[nf][1]));
                rmx1 = fmaxf(rmx1, fmaxf(v[nf][2], v[nf][3]));
            }
            rmx0 = fmaxf(rmx0, __shfl_xor_sync(0xffffffff, rmx0, 1));
            rmx0 = fmaxf(rmx0, __shfl_xor_sync(0xffffffff, rmx0, 2));
            rmx1 = fmaxf(rmx1, __shfl_xor_sync(0xffffffff, rmx1, 1));
            rmx1 = fmaxf(rmx1, __shfl_xor_sync(0xffffffff, rmx1, 2));

            float mn0 = fmaxf(mB[0], rmx0), mn1 = fmaxf(mB[1], rmx1);
            float al0 = __expf(mB[0] - mn0), al1 = __expf(mB[1] - mn1);
            float rs0 = 0.f, rs1 = 0.f;
            #pragma unroll
            for (int nf = 0; nf < 8; nf++) {
                v[nf][0] = __expf(v[nf][0] - mn0);
                v[nf][1] = __expf(v[nf][1] - mn0);
                v[nf][2] = __expf(v[nf][2] - mn1);
                v[nf][3] = __expf(v[nf][3] - mn1);
                rs0 += v[nf][0] + v[nf][1];
                rs1 += v[nf][2] + v[nf][3];
            }
            rs0 += __shfl_xor_sync(0xffffffff, rs0, 1);
            rs0 += __shfl_xor_sync(0xffffffff, rs0, 2);
            rs1 += __shfl_xor_sync(0xffffffff, rs1, 1);
            rs1 += __shfl_xor_sync(0xffffffff, rs1, 2);
            lB[0] = lB[0] * al0 + rs0; lB[1] = lB[1] * al1 + rs1;
            mB[0] = mn0; mB[1] = mn1;

            #pragma unroll
            for (int nf = 0; nf < 8; nf++) {
                OB[nf][0] *= al0; OB[nf][1] *= al0;
                OB[nf][2] *= al1; OB[nf][3] *= al1;
                v[nf][0] = __uint_as_float(f2tf(v[nf][0]));
                v[nf][1] = __uint_as_float(f2tf(v[nf][1]));
                v[nf][2] = __uint_as_float(f2tf(v[nf][2]));
                v[nf][3] = __uint_as_float(f2tf(v[nf][3]));
            }

            // P @ V
            #pragma unroll
            for (int kc = 0; kc < 8; kc++) {
                float x0 = __shfl_sync(0xffffffff, v[kc][0], srcA);
                float x1 = __shfl_sync(0xffffffff, v[kc][1], srcA);
                float x2 = __shfl_sync(0xffffffff, v[kc][2], srcA);
                float x3 = __shfl_sync(0xffffffff, v[kc][3], srcA);
                float y0 = __shfl_sync(0xffffffff, v[kc][0], srcB);
                float y1 = __shfl_sync(0xffffffff, v[kc][1], srcB);
                float y2 = __shfl_sync(0xffffffff, v[kc][2], srcB);
                float y3 = __shfl_sync(0xffffffff, v[kc][3], srcB);
                uint32_t a[4];
                a[0] = __float_as_uint(odd ? x1 : x0);
                a[1] = __float_as_uint(odd ? x3 : x2);
                a[2] = __float_as_uint(odd ? y1 : y0);
                a[3] = __float_as_uint(odd ? y3 : y2);
                #pragma unroll
                for (int nf = 0; nf < 8; nf++) {
                    uint32_t bf[2];
                    bf[0] = __float_as_uint(sV_[(kc * 8 + q_) * 72 + nf * 8 + p_]);
                    bf[1] = __float_as_uint(sV_[(kc * 8 + q_ + 4) * 72 + nf * 8 + p_]);
                    mma_tf32(OB[nf], a, bf);
                }
            }
        }
    }

    // epilogue: normalize + store into cat
    float rl10 = 1.f / l1[0], rl11 = 1.f / l1[1];
    float rl20 = 1.f / l2[0], rl21 = 1.f / l2[1];
    int row = q0 + wrow0 + p_;
    #pragma unroll
    for (int nf = 0; nf < 8; nf++) {
        int col = h * 64 + nf * 8 + 2 * q_;
        float2 o;
        o.x = O1[nf][0] * rl10; o.y = O1[nf][1] * rl10;
        *(float2*)(cat + (size_t)row * D2 + col) = o;
        o.x = O1[nf][2] * rl11; o.y = O1[nf][3] * rl11;
        *(float2*)(cat + (size_t)(row + 8) * D2 + col) = o;
        o.x = O2[nf][0] * rl20; o.y = O2[nf][1] * rl20;
        *(float2*)(cat + (size_t)row * D2 + D + col) = o;
        o.x = O2[nf][2] * rl21; o.y = O2[nf][3] * rl21;
        *(float2*)(cat + (size_t)(row + 8) * D2 + D + col) = o;
    }

    float tot = blockReduceSum(ssum);
    if (tid == 0) atomicAdd(&g_sigacc, (double)tot);
}

// ---------------- sigmoid mean over strictly-upper region ----------------
__global__ __launch_bounds__(256) void k_sig_upper(const float* __restrict__ lm)
{
    int qi = blockIdx.x;           // 0..14
    int h  = blockIdx.y;
    int q0 = qi * 128;
    int c0 = (qi + 1) * 128;
    int cols4 = (T - c0) >> 2;
    int n = 128 * cols4;
    float ssum = 0.f;
    for (int i = threadIdx.x; i < n; i += 256) {
        int row = i / cols4;
        int cc  = (i - row * cols4) * 4;
        float4 v = *(const float4*)(lm + ((size_t)h * T + q0 + row) * T + c0 + cc);
        ssum += sigf(v.x) + sigf(v.y) + sigf(v.z) + sigf(v.w);
    }
    float tot = blockReduceSum(ssum);
    if (threadIdx.x == 0) atomicAdd(&g_sigacc, (double)tot);
}

__global__ void k_zero_acc() { g_sigacc = 0.0; }

__global__ void k_write_sp(float* out, int out_size)
{
    const long long TD = (long long)T * D;
    if (out_size > TD) {
        double mean = g_sigacc / ((double)H * (double)T * (double)T);
        out[TD] = (float)(SPARSITY_LAMBDA * mean);
    }
}

// ---------------- launch ----------------
#define NT_SMEM (6 * NT_STAGE * sizeof(float))   // 110592
#define FL_SMEM (44032 * sizeof(float))          // 176128

extern "C" void kernel_launch(void* const* d_in, const int* in_sizes, int n_in,
                              void* d_out, int out_size)
{
    const float* x      = (const float*)d_in[0];
    const float* W_qkv  = (const float*)d_in[2];
    const float* W_out  = (const float*)d_in[3];
    const float* logm   = (const float*)d_in[4];
    const float* W_gate = (const float*)d_in[5];
    const float* b_gate = (const float*)d_in[6];
    const float* g1     = (const float*)d_in[7];
    const float* b1     = (const float*)d_in[8];
    const float* g2     = (const float*)d_in[9];
    const float* b2     = (const float*)d_in[10];
    const float* W_ff1  = (const float*)d_in[11];
    const float* b_ff1  = (const float*)d_in[12];
    const float* W_ff2  = (const float*)d_in[13];
    const float* b_ff2  = (const float*)d_in[14];
    float* out = (float*)d_out;

    float *xn, *qkv, *cat, *tmp, *hbuf, *hn, *ff;
    cudaGetSymbolAddress((void**)&xn,   g_xn);
    cudaGetSymbolAddress((void**)&qkv,  g_qkv);
    cudaGetSymbolAddress((void**)&cat,  g_cat);
    cudaGetSymbolAddress((void**)&tmp,  g_tmp);
    cudaGetSymbolAddress((void**)&hbuf, g_h);
    cudaGetSymbolAddress((void**)&hn,   g_hn);
    cudaGetSymbolAddress((void**)&ff,   g_ff);

    cudaFuncSetAttribute(k_mm_nt<false, false, false, true >, cudaFuncAttributeMaxDynamicSharedMemorySize, NT_SMEM);
    cudaFuncSetAttribute(k_mm_nt<false, true,  false, false>, cudaFuncAttributeMaxDynamicSharedMemorySize, NT_SMEM);
    cudaFuncSetAttribute(k_mm_nt<false, false, true,  false>, cudaFuncAttributeMaxDynamicSharedMemorySize, NT_SMEM);
    cudaFuncSetAttribute(k_mm_nt<true,  true,  false, false>, cudaFuncAttributeMaxDynamicSharedMemorySize, NT_SMEM);
    cudaFuncSetAttribute(k_mm_nt<false, true,  true,  false>, cudaFuncAttributeMaxDynamicSharedMemorySize, NT_SMEM);
    cudaFuncSetAttribute(k_flash, cudaFuncAttributeMaxDynamicSharedMemorySize, FL_SMEM);

    k_zero_acc<<<1, 1>>>();

    // ln1
    k_layernorm<<<T, 256>>>(x, g1, b1, xn);

    // qkv = xn @ W_qkv^T, output rounded to tf32 for the flash kernel
    k_mm_nt<false, false, false, true><<<dim3(D3 / 128, T / 128), 256, NT_SMEM>>>(
        xn, D, W_qkv, D, qkv, D3, D, 1.f, nullptr, nullptr, 0);

    // sigmoid-mean over the strictly-upper region
    k_sig_upper<<<dim3(15, H), 256>>>(logm);

    // fused dual-softmax attention -> cat
    k_flash<<<256, 256, FL_SMEM>>>(qkv, logm, cat);

    // tmp = cat @ W_gate^T + b_gate
    k_mm_nt<false, true, false, false><<<dim3(D / 128, T / 128), 256, NT_SMEM>>>(
        cat, D2, W_gate, D2, tmp, D, D2, 1.f, b_gate, nullptr, 0);

    // h = x + tmp @ W_out^T
    k_mm_nt<false, false, true, false><<<dim3(D / 128, T / 128), 256, NT_SMEM>>>(
        tmp, D, W_out, D, hbuf, D, D, 1.f, nullptr, x, D);

    // ln2
    k_layernorm<<<T, 256>>>(hbuf, g2, b2, hn);

    // ff = gelu(hn @ W_ff1^T + b_ff1)
    k_mm_nt<true, true, false, false><<<dim3(DFF / 128, T / 128), 256, NT_SMEM>>>(
        hn, D, W_ff1, D, ff, DFF, D, 1.f, b_ff1, nullptr, 0);

    // out = h + ff @ W_ff2^T + b_ff2
    k_mm_nt<false, true, true, false><<<dim3(D / 128, T / 128), 256, NT_SMEM>>>(
        ff, DFF, W_ff2, DFF, out, D, DFF, 1.f, b_ff2, hbuf, D);

    k_write_sp<<<1, 1>>>(out, out_size);
}

// round 6
// speedup vs baseline: 3.5261x; 1.1646x over previous
#include <cuda_runtime.h>
#include <cuda_bf16.h>
#include <math_constants.h>
#include <cstdint>

#define T 2048
#define D 1024
#define H 16
#define DH 64
#define D3 3072
#define D2 2048
#define DFF 4096
#define LN_EPS 1e-5f
#define SPARSITY_LAMBDA 0.0005f

// ---------------- scratch ----------------
__device__ float g_xn[(size_t)T * D];
__device__ float g_qkv[(size_t)T * D3];
__device__ float g_cat[(size_t)T * D2];
__device__ float g_tmp[(size_t)T * D];
__device__ float g_h[(size_t)T * D];
__device__ float g_hn[(size_t)T * D];
__device__ float g_ff[(size_t)T * DFF];
__device__ double g_sigacc;

// ---------------- helpers ----------------
__device__ __forceinline__ uint32_t f2tf(float f) {
    uint32_t u;
    asm("cvt.rna.tf32.f32 %0, %1;" : "=r"(u) : "f"(f));
    return u;
}

__device__ __forceinline__ void mma_tf32(float (&d)[4], const uint32_t (&a)[4], const uint32_t (&b)[2]) {
    asm volatile(
        "mma.sync.aligned.m16n8k8.row.col.f32.tf32.tf32.f32 "
        "{%0,%1,%2,%3}, {%4,%5,%6,%7}, {%8,%9}, {%0,%1,%2,%3};\n"
        : "+f"(d[0]), "+f"(d[1]), "+f"(d[2]), "+f"(d[3])
        : "r"(a[0]), "r"(a[1]), "r"(a[2]), "r"(a[3]), "r"(b[0]), "r"(b[1]));
}

__device__ __forceinline__ void cp16(float* sdst, const float* gsrc) {
    uint32_t s = (uint32_t)__cvta_generic_to_shared(sdst);
    asm volatile("cp.async.cg.shared.global [%0], [%1], 16;" :: "r"(s), "l"(gsrc));
}
__device__ __forceinline__ void cp_commit() { asm volatile("cp.async.commit_group;"); }
template<int N> __device__ __forceinline__ void cp_wait() {
    asm volatile("cp.async.wait_group %0;" :: "n"(N));
}

__device__ __forceinline__ float sigf(float x) { return 1.f / (1.f + __expf(-x)); }

__device__ __forceinline__ float blockReduceSum(float v) {
    __shared__ float red[32];
    int lane = threadIdx.x & 31, wid = threadIdx.x >> 5;
    #pragma unroll
    for (int o = 16; o > 0; o >>= 1) v += __shfl_xor_sync(0xffffffff, v, o);
    __syncthreads();
    if (lane == 0) red[wid] = v;
    __syncthreads();
    int nw = (blockDim.x + 31) >> 5;
    float r = (threadIdx.x < nw) ? red[threadIdx.x] : 0.f;
    if (wid == 0) {
        #pragma unroll
        for (int o = 16; o > 0; o >>= 1) r += __shfl_xor_sync(0xffffffff, r, o);
        if (lane == 0) red[0] = r;
    }
    __syncthreads();
    return red[0];
}

// ---------------- layernorm ----------------
__global__ __launch_bounds__(256) void k_layernorm(
    const float* __restrict__ x, const float* __restrict__ g,
    const float* __restrict__ b, float* __restrict__ out)
{
    int t = blockIdx.x;
    const float* xr = x + (size_t)t * D;
    float s = 0.f, s2 = 0.f;
    for (int i = threadIdx.x; i < D; i += 256) {
        float v = xr[i];
        s += v; s2 += v * v;
    }
    float tot = blockReduceSum(s);
    float tot2 = blockReduceSum(s2);
    float mean = tot * (1.f / D);
    float var = tot2 * (1.f / D) - mean * mean;
    float rstd = rsqrtf(var + LN_EPS);
    float* orow = out + (size_t)t * D;
    for (int i = threadIdx.x; i < D; i += 256) {
        orow[i] = (xr[i] - mean) * rstd * g[i] + b[i];
    }
}

// ---------------- TF32 GEMM NT, cp.async 3-stage ----------------
#define NT_STAGE 4608   // 128*36 floats
template<bool GELU, bool HASBIAS, bool HASRES, bool ROUND>
__global__ __launch_bounds__(256) void k_mm_nt(
    const float* __restrict__ A, int lda,
    const float* __restrict__ B, int ldb,
    float* __restrict__ C, int ldc,
    int K, float scale,
    const float* __restrict__ bias,
    const float* __restrict__ res, int ldres)
{
    int m0 = blockIdx.y * 128, n0 = blockIdx.x * 128;
    A += (long long)m0 * lda;
    B += (long long)n0 * ldb;

    extern __shared__ float sm_nt[];
    float* Abuf = sm_nt;                // [3][128][36]
    float* Bbuf = sm_nt + 3 * NT_STAGE; // [3][128][36]

    int tid = threadIdx.x, lane = tid & 31, warp = tid >> 5;
    int wm = (warp & 1) * 64, wn = (warp >> 1) * 32;
    int lr = tid >> 3, lc = (tid & 7) * 4;

    float acc[4][4][4] = {};

    auto load = [&](int st, int k0) {
        float* As_ = Abuf + st * NT_STAGE;
        float* Bs_ = Bbuf + st * NT_STAGE;
        #pragma unroll
        for (int p = 0; p < 4; p++) {
            int row = p * 32 + lr;
            cp16(As_ + row * 36 + lc, A + (long long)row * lda + k0 + lc);
            cp16(Bs_ + row * 36 + lc, B + (long long)row * ldb + k0 + lc);
        }
    };

    int nk = K / 32;
    load(0, 0); cp_commit();
    load(1, 32); cp_commit();

    for (int i = 0; i < nk; i++) {
        if (i + 1 < nk) cp_wait<1>(); else cp_wait<0>();
        __syncthreads();
        if (i + 2 < nk) { load((i + 2) % 3, (i + 2) * 32); cp_commit(); }

        const float* As_ = Abuf + (i % 3) * NT_STAGE;
        const float* Bs_ = Bbuf + (i % 3) * NT_STAGE;
        #pragma unroll
        for (int ks = 0; ks < 4; ks++) {
            int kb = ks * 8 + (lane & 3);
            uint32_t af[4][4], bf[4][2];
            #pragma unroll
            for (int mf = 0; mf < 4; mf++) {
                int r = wm + mf * 16 + (lane >> 2);
                af[mf][0] = f2tf(As_[r * 36 + kb]);
                af[mf][1] = f2tf(As_[(r + 8) * 36 + kb]);
                af[mf][2] = f2tf(As_[r * 36 + kb + 4]);
                af[mf][3] = f2tf(As_[(r + 8) * 36 + kb + 4]);
            }
            #pragma unroll
            for (int nf = 0; nf < 4; nf++) {
                int r = wn + nf * 8 + (lane >> 2);
                bf[nf][0] = f2tf(Bs_[r * 36 + kb]);
                bf[nf][1] = f2tf(Bs_[r * 36 + kb + 4]);
            }
            #pragma unroll
            for (int mf = 0; mf < 4; mf++)
                #pragma unroll
                for (int nf = 0; nf < 4; nf++)
                    mma_tf32(acc[mf][nf], af[mf], bf[nf]);
        }
    }

    #pragma unroll
    for (int mf = 0; mf < 4; mf++) {
        int row = m0 + wm + mf * 16 + (lane >> 2);
        #pragma unroll
        for (int nf = 0; nf < 4; nf++) {
            int col = n0 + wn + nf * 8 + 2 * (lane & 3);
            #pragma unroll
            for (int half = 0; half < 2; half++) {
                int r = row + half * 8;
                float v0 = acc[mf][nf][half * 2 + 0] * scale;
                float v1 = acc[mf][nf][half * 2 + 1] * scale;
                if (HASBIAS) { v0 += bias[col]; v1 += bias[col + 1]; }
                if (GELU) {
                    v0 = 0.5f * v0 * (1.f + erff(v0 * 0.70710678118654752f));
                    v1 = 0.5f * v1 * (1.f + erff(v1 * 0.70710678118654752f));
                }
                if (HASRES) {
                    v0 += res[(long long)r * ldres + col];
                    v1 += res[(long long)r * ldres + col + 1];
                }
                if (ROUND) {
                    v0 = __uint_as_float(f2tf(v0));
                    v1 = __uint_as_float(f2tf(v1));
                }
                float2 o = {v0, v1};
                *(float2*)(C + (long long)r * ldc + col) = o;
            }
        }
    }
}

// ---------------- fused dual-softmax flash attention ----------------
__global__ __launch_bounds__(256) void k_flash(
    const float* __restrict__ qkv, const float* __restrict__ logm,
    float* __restrict__ cat)
{
    extern __shared__ float sm[];
    float* sQ = sm;             // [128][68]
    float* sK = sm + 8704;      // [2][64][68]
    float* sV = sm + 17408;     // [2][64][72]
    float* sM = sm + 26624;     // [2][128][68]

    int bid = blockIdx.x;
    int qi = 15 - (bid >> 4);   // heavy blocks first
    int h  = bid & 15;
    int q0 = qi * 128;
    int nkb = 2 * (qi + 1);

    int tid = threadIdx.x, lane = tid & 31, warp = tid >> 5;
    int p_ = lane >> 2, q_ = lane & 3;
    int wrow0 = warp * 16;

    #pragma unroll
    for (int i = 0; i < 8; i++) {
        int idx = tid + i * 256;
        int row = idx >> 4, c4 = (idx & 15) * 4;
        cp16(sQ + row * 68 + c4, qkv + (size_t)(q0 + row) * D3 + h * 64 + c4);
    }
    #pragma unroll
    for (int i = 0; i < 4; i++) {
        int idx = tid + i * 256;
        int row = idx >> 4, c4 = (idx & 15) * 4;
        cp16(sK + row * 68 + c4, qkv + (size_t)row * D3 + D + h * 64 + c4);
        cp16(sV + row * 72 + c4, qkv + (size_t)row * D3 + 2 * D + h * 64 + c4);
    }
    #pragma unroll
    for (int i = 0; i < 8; i++) {
        int idx = tid + i * 256;
        int row = idx >> 4, c4 = (idx & 15) * 4;
        cp16(sM + row * 68 + c4, logm + ((size_t)h * T + q0 + row) * T + c4);
    }
    cp_commit();

    float O1[8][4] = {}, O2[8][4] = {};
    float m1[2] = {-1e30f, -1e30f}, l1[2] = {0.f, 0.f};
    float m2[2] = {-1e30f, -1e30f}, l2[2] = {0.f, 0.f};

    int r0 = wrow0 + p_;
    int t0 = q0 + r0, t1 = t0 + 8;
    int srcA = (lane & ~3) | (q_ >> 1);
    int srcB = srcA + 2;
    bool odd = q_ & 1;

    for (int j = 0; j < nkb; j++) {
        int st = j & 1;
        int kb0 = j * 64;
        cp_wait<0>();
        __syncthreads();
        if (j + 1 < nkb) {
            int st2 = st ^ 1, kb2 = kb0 + 64;
            float* dK = sK + st2 * 4352;
            float* dV = sV + st2 * 4608;
            float* dM = sM + st2 * 8704;
            #pragma unroll
            for (int i = 0; i < 4; i++) {
                int idx = tid + i * 256;
                int row = idx >> 4, c4 = (idx & 15) * 4;
                cp16(dK + row * 68 + c4, qkv + (size_t)(kb2 + row) * D3 + D + h * 64 + c4);
                cp16(dV + row * 72 + c4, qkv + (size_t)(kb2 + row) * D3 + 2 * D + h * 64 + c4);
            }
            #pragma unroll
            for (int i = 0; i < 8; i++) {
                int idx = tid + i * 256;
                int row = idx >> 4, c4 = (idx & 15) * 4;
                cp16(dM + row * 68 + c4, logm + ((size_t)h * T + q0 + row) * T + kb2 + c4);
            }
            cp_commit();
        }

        if (kb0 > q0 + wrow0 + 15) continue;   // tile fully above diagonal

        const float* sK_ = sK + st * 4352;
        const float* sV_ = sV + st * 4608;
        const float* sM_ = sM + st * 8704;

        float sg[8][4];
        #pragma unroll
        for (int nf = 0; nf < 8; nf++) {
            int c0 = nf * 8 + 2 * q_;
            float2 a = *(const float2*)(sM_ + r0 * 68 + c0);
            float2 b = *(const float2*)(sM_ + (r0 + 8) * 68 + c0);
            sg[nf][0] = sigf(a.x); sg[nf][1] = sigf(a.y);
            sg[nf][2] = sigf(b.x); sg[nf][3] = sigf(b.y);
        }

        float sc[8][4] = {};
        #pragma unroll
        for (int kc = 0; kc < 8; kc++) {
            int kb = kc * 8 + q_;
            uint32_t af[4];
            af[0] = __float_as_uint(sQ[r0 * 68 + kb]);
            af[1] = __float_as_uint(sQ[(r0 + 8) * 68 + kb]);
            af[2] = __float_as_uint(sQ[r0 * 68 + kb + 4]);
            af[3] = __float_as_uint(sQ[(r0 + 8) * 68 + kb + 4]);
            #pragma unroll
            for (int nf = 0; nf < 8; nf++) {
                uint32_t bf[2];
                bf[0] = __float_as_uint(sK_[(nf * 8 + p_) * 68 + kb]);
                bf[1] = __float_as_uint(sK_[(nf * 8 + p_) * 68 + kb + 4]);
                mma_tf32(sc[nf], af, bf);
            }
        }
        #pragma unroll
        for (int nf = 0; nf < 8; nf++) {
            sc[nf][0] *= 0.125f; sc[nf][1] *= 0.125f;
            sc[nf][2] *= 0.125f; sc[nf][3] *= 0.125f;
        }

        #pragma unroll
        for (int br = 0; br < 2; br++) {
            float* mB = br ? m2 : m1;
            float* lB = br ? l2 : l1;
            float (*OB)[4] = br ? O2 : O1;

            float v[8][4];
            float rmx0 = -1e30f, rmx1 = -1e30f;
            #pragma unroll
            for (int nf = 0; nf < 8; nf++) {
                int c0 = kb0 + nf * 8 + 2 * q_;
                float w0 = br ? sc[nf][0] * sg[nf][0] : sc[nf][0];
                float w1 = br ? sc[nf][1] * sg[nf][1] : sc[nf][1];
                float w2 = br ? sc[nf][2] * sg[nf][2] : sc[nf][2];
                float w3 = br ? sc[nf][3] * sg[nf][3] : sc[nf][3];
                v[nf][0] = (c0     <= t0) ? w0 : -1e30f;
                v[nf][1] = (c0 + 1 <= t0) ? w1 : -1e30f;
                v[nf][2] = (c0     <= t1) ? w2 : -1e30f;
                v[nf][3] = (c0 + 1 <= t1) ? w3 : -1e30f;
                rmx0 = fmaxf(rmx0, fmaxf(v[nf][0], v[nf][1]));
                rmx1 = fmaxf(rmx1, fmaxf(v[nf][2], v[nf][3]));
            }
            rmx0 = fmaxf(rmx0, __shfl_xor_sync(0xffffffff, rmx0, 1));
            rmx0 = fmaxf(rmx0, __shfl_xor_sync(0xffffffff, rmx0, 2));
            rmx1 = fmaxf(rmx1, __shfl_xor_sync(0xffffffff, rmx1, 1));
            rmx1 = fmaxf(rmx1, __shfl_xor_sync(0xffffffff, rmx1, 2));

            float mn0 = fmaxf(mB[0], rmx0), mn1 = fmaxf(mB[1], rmx1);
            float al0 = __expf(mB[0] - mn0), al1 = __expf(mB[1] - mn1);
            float rs0 = 0.f, rs1 = 0.f;
            #pragma unroll
            for (int nf = 0; nf < 8; nf++) {
                v[nf][0] = __expf(v[nf][0] - mn0);
                v[nf][1] = __expf(v[nf][1] - mn0);
                v[nf][2] = __expf(v[nf][2] - mn1);
                v[nf][3] = __expf(v[nf][3] - mn1);
                rs0 += v[nf][0] + v[nf][1];
                rs1 += v[nf][2] + v[nf][3];
            }
            rs0 += __shfl_xor_sync(0xffffffff, rs0, 1);
            rs0 += __shfl_xor_sync(0xffffffff, rs0, 2);
            rs1 += __shfl_xor_sync(0xffffffff, rs1, 1);
            rs1 += __shfl_xor_sync(0xffffffff, rs1, 2);
            lB[0] = lB[0] * al0 + rs0; lB[1] = lB[1] * al1 + rs1;
            mB[0] = mn0; mB[1] = mn1;

            #pragma unroll
            for (int nf = 0; nf < 8; nf++) {
                OB[nf][0] *= al0; OB[nf][1] *= al0;
                OB[nf][2] *= al1; OB[nf][3] *= al1;
                v[nf][0] = __uint_as_float(f2tf(v[nf][0]));
                v[nf][1] = __uint_as_float(f2tf(v[nf][1]));
                v[nf][2] = __uint_as_float(f2tf(v[nf][2]));
                v[nf][3] = __uint_as_float(f2tf(v[nf][3]));
            }

            #pragma unroll
            for (int kc = 0; kc < 8; kc++) {
                float x0 = __shfl_sync(0xffffffff, v[kc][0], srcA);
                float x1 = __shfl_sync(0xffffffff, v[kc][1], srcA);
                float x2 = __shfl_sync(0xffffffff, v[kc][2], srcA);
                float x3 = __shfl_sync(0xffffffff, v[kc][3], srcA);
                float y0 = __shfl_sync(0xffffffff, v[kc][0], srcB);
                float y1 = __shfl_sync(0xffffffff, v[kc][1], srcB);
                float y2 = __shfl_sync(0xffffffff, v[kc][2], srcB);
                float y3 = __shfl_sync(0xffffffff, v[kc][3], srcB);
                uint32_t a[4];
                a[0] = __float_as_uint(odd ? x1 : x0);
                a[1] = __float_as_uint(odd ? x3 : x2);
                a[2] = __float_as_uint(odd ? y1 : y0);
                a[3] = __float_as_uint(odd ? y3 : y2);
                #pragma unroll
                for (int nf = 0; nf < 8; nf++) {
                    uint32_t bf[2];
                    bf[0] = __float_as_uint(sV_[(kc * 8 + q_) * 72 + nf * 8 + p_]);
                    bf[1] = __float_as_uint(sV_[(kc * 8 + q_ + 4) * 72 + nf * 8 + p_]);
                    mma_tf32(OB[nf], a, bf);
                }
            }
        }
    }

    float rl10 = 1.f / l1[0], rl11 = 1.f / l1[1];
    float rl20 = 1.f / l2[0], rl21 = 1.f / l2[1];
    int row = q0 + wrow0 + p_;
    #pragma unroll
    for (int nf = 0; nf < 8; nf++) {
        int col = h * 64 + nf * 8 + 2 * q_;
        float2 o;
        o.x = O1[nf][0] * rl10; o.y = O1[nf][1] * rl10;
        *(float2*)(cat + (size_t)row * D2 + col) = o;
        o.x = O1[nf][2] * rl11; o.y = O1[nf][3] * rl11;
        *(float2*)(cat + (size_t)(row + 8) * D2 + col) = o;
        o.x = O2[nf][0] * rl20; o.y = O2[nf][1] * rl20;
        *(float2*)(cat + (size_t)row * D2 + D + col) = o;
        o.x = O2[nf][2] * rl21; o.y = O2[nf][3] * rl21;
        *(float2*)(cat + (size_t)(row + 8) * D2 + D + col) = o;
    }
}

// ---------------- sigmoid mean over the FULL mask (flat, full-chip) ----------------
__global__ __launch_bounds__(256) void k_sigsum(const float* __restrict__ lm)
{
    const size_t n4 = (size_t)H * T * T / 4;
    const float4* p = (const float4*)lm;
    float s = 0.f;
    for (size_t i = (size_t)blockIdx.x * 256 + threadIdx.x; i < n4;
         i += (size_t)gridDim.x * 256) {
        float4 v = p[i];
        s += sigf(v.x) + sigf(v.y) + sigf(v.z) + sigf(v.w);
    }
    float tot = blockReduceSum(s);
    if (threadIdx.x == 0) atomicAdd(&g_sigacc, (double)tot);
}

__global__ void k_zero_acc() { g_sigacc = 0.0; }

__global__ void k_write_sp(float* out, int out_size)
{
    const long long TD = (long long)T * D;
    if (out_size > TD) {
        double mean = g_sigacc / ((double)H * (double)T * (double)T);
        out[TD] = (float)(SPARSITY_LAMBDA * mean);
    }
}

// ---------------- launch ----------------
#define NT_SMEM (6 * NT_STAGE * sizeof(float))   // 110592
#define FL_SMEM (44032 * sizeof(float))          // 176128

extern "C" void kernel_launch(void* const* d_in, const int* in_sizes, int n_in,
                              void* d_out, int out_size)
{
    const float* x      = (const float*)d_in[0];
    const float* W_qkv  = (const float*)d_in[2];
    const float* W_out  = (const float*)d_in[3];
    const float* logm   = (const float*)d_in[4];
    const float* W_gate = (const float*)d_in[5];
    const float* b_gate = (const float*)d_in[6];
    const float* g1     = (const float*)d_in[7];
    const float* b1     = (const float*)d_in[8];
    const float* g2     = (const float*)d_in[9];
    const float* b2     = (const float*)d_in[10];
    const float* W_ff1  = (const float*)d_in[11];
    const float* b_ff1  = (const float*)d_in[12];
    const float* W_ff2  = (const float*)d_in[13];
    const float* b_ff2  = (const float*)d_in[14];
    float* out = (float*)d_out;

    float *xn, *qkv, *cat, *tmp, *hbuf, *hn, *ff;
    cudaGetSymbolAddress((void**)&xn,   g_xn);
    cudaGetSymbolAddress((void**)&qkv,  g_qkv);
    cudaGetSymbolAddress((void**)&cat,  g_cat);
    cudaGetSymbolAddress((void**)&tmp,  g_tmp);
    cudaGetSymbolAddress((void**)&hbuf, g_h);
    cudaGetSymbolAddress((void**)&hn,   g_hn);
    cudaGetSymbolAddress((void**)&ff,   g_ff);

    cudaFuncSetAttribute(k_mm_nt<false, false, false, true >, cudaFuncAttributeMaxDynamicSharedMemorySize, NT_SMEM);
    cudaFuncSetAttribute(k_mm_nt<false, true,  false, false>, cudaFuncAttributeMaxDynamicSharedMemorySize, NT_SMEM);
    cudaFuncSetAttribute(k_mm_nt<false, false, true,  false>, cudaFuncAttributeMaxDynamicSharedMemorySize, NT_SMEM);
    cudaFuncSetAttribute(k_mm_nt<true,  true,  false, false>, cudaFuncAttributeMaxDynamicSharedMemorySize, NT_SMEM);
    cudaFuncSetAttribute(k_mm_nt<false, true,  true,  false>, cudaFuncAttributeMaxDynamicSharedMemorySize, NT_SMEM);
    cudaFuncSetAttribute(k_flash, cudaFuncAttributeMaxDynamicSharedMemorySize, FL_SMEM);

    k_zero_acc<<<1, 1>>>();

    // ln1
    k_layernorm<<<T, 256>>>(x, g1, b1, xn);

    // qkv = xn @ W_qkv^T, output rounded to tf32 for the flash kernel
    k_mm_nt<false, false, false, true><<<dim3(D3 / 128, T / 128), 256, NT_SMEM>>>(
        xn, D, W_qkv, D, qkv, D3, D, 1.f, nullptr, nullptr, 0);

    // sigmoid-mean over the full mask (flat grid-stride, full chip)
    k_sigsum<<<1184, 256>>>(logm);

    // fused dual-softmax attention -> cat
    k_flash<<<256, 256, FL_SMEM>>>(qkv, logm, cat);

    // tmp = cat @ W_gate^T + b_gate
    k_mm_nt<false, true, false, false><<<dim3(D / 128, T / 128), 256, NT_SMEM>>>(
        cat, D2, W_gate, D2, tmp, D, D2, 1.f, b_gate, nullptr, 0);

    // h = x + tmp @ W_out^T
    k_mm_nt<false, false, true, false><<<dim3(D / 128, T / 128), 256, NT_SMEM>>>(
        tmp, D, W_out, D, hbuf, D, D, 1.f, nullptr, x, D);

    // ln2
    k_layernorm<<<T, 256>>>(hbuf, g2, b2, hn);

    // ff = gelu(hn @ W_ff1^T + b_ff1)
    k_mm_nt<true, true, false, false><<<dim3(DFF / 128, T / 128), 256, NT_SMEM>>>(
        hn, D, W_ff1, D, ff, DFF, D, 1.f, b_ff1, nullptr, 0);

    // out = h + ff @ W_ff2^T + b_ff2
    k_mm_nt<false, true, true, false><<<dim3(D / 128, T / 128), 256, NT_SMEM>>>(
        ff, DFF, W_ff2, DFF, out, D, DFF, 1.f, b_ff2, hbuf, D);

    k_write_sp<<<1, 1>>>(out, out_size);
}

// round 7
// speedup vs baseline: 4.3347x; 1.2293x over previous
#include <cuda_runtime.h>
#include <cuda_fp16.h>
#include <math_constants.h>
#include <cstdint>

#define T 2048
#define D 1024
#define H 16
#define DH 64
#define D3 3072
#define D2 2048
#define DFF 4096
#define LN_EPS 1e-5f
#define SPARSITY_LAMBDA 0.0005f

// ---------------- scratch ----------------
__device__ __half g_xnh[(size_t)T * D];
__device__ float  g_qkv[(size_t)T * D3];
__device__ __half g_cath[(size_t)T * D2];
__device__ __half g_tmph[(size_t)T * D];
__device__ float  g_h[(size_t)T * D];
__device__ __half g_hnh[(size_t)T * D];
__device__ __half g_ffh[(size_t)T * DFF];
__device__ __half g_wqkvh[(size_t)D3 * D];
__device__ __half g_wgateh[(size_t)D * D2];
__device__ __half g_wouth[(size_t)D * D];
__device__ __half g_wff1h[(size_t)DFF * D];
__device__ __half g_wff2h[(size_t)D * DFF];
__device__ double g_sigacc;

// ---------------- helpers ----------------
__device__ __forceinline__ uint32_t f2tf(float f) {
    uint32_t u;
    asm("cvt.rna.tf32.f32 %0, %1;" : "=r"(u) : "f"(f));
    return u;
}

__device__ __forceinline__ void mma_tf32(float (&d)[4], const uint32_t (&a)[4], const uint32_t (&b)[2]) {
    asm volatile(
        "mma.sync.aligned.m16n8k8.row.col.f32.tf32.tf32.f32 "
        "{%0,%1,%2,%3}, {%4,%5,%6,%7}, {%8,%9}, {%0,%1,%2,%3};\n"
        : "+f"(d[0]), "+f"(d[1]), "+f"(d[2]), "+f"(d[3])
        : "r"(a[0]), "r"(a[1]), "r"(a[2]), "r"(a[3]), "r"(b[0]), "r"(b[1]));
}

__device__ __forceinline__ void mma_f16(float (&d)[4], const uint32_t (&a)[4], const uint32_t (&b)[2]) {
    asm volatile(
        "mma.sync.aligned.m16n8k16.row.col.f32.f16.f16.f32 "
        "{%0,%1,%2,%3}, {%4,%5,%6,%7}, {%8,%9}, {%0,%1,%2,%3};\n"
        : "+f"(d[0]), "+f"(d[1]), "+f"(d[2]), "+f"(d[3])
        : "r"(a[0]), "r"(a[1]), "r"(a[2]), "r"(a[3]), "r"(b[0]), "r"(b[1]));
}

__device__ __forceinline__ void cp16(void* sdst, const void* gsrc) {
    uint32_t s = (uint32_t)__cvta_generic_to_shared(sdst);
    asm volatile("cp.async.cg.shared.global [%0], [%1], 16;" :: "r"(s), "l"(gsrc));
}
__device__ __forceinline__ void cp_commit() { asm volatile("cp.async.commit_group;"); }
template<int N> __device__ __forceinline__ void cp_wait() {
    asm volatile("cp.async.wait_group %0;" :: "n"(N));
}

__device__ __forceinline__ float sigf(float x) { return 1.f / (1.f + __expf(-x)); }

__device__ __forceinline__ float blockReduceSum(float v) {
    __shared__ float red[32];
    int lane = threadIdx.x & 31, wid = threadIdx.x >> 5;
    #pragma unroll
    for (int o = 16; o > 0; o >>= 1) v += __shfl_xor_sync(0xffffffff, v, o);
    __syncthreads();
    if (lane == 0) red[wid] = v;
    __syncthreads();
    int nw = (blockDim.x + 31) >> 5;
    float r = (threadIdx.x < nw) ? red[threadIdx.x] : 0.f;
    if (wid == 0) {
        #pragma unroll
        for (int o = 16; o > 0; o >>= 1) r += __shfl_xor_sync(0xffffffff, r, o);
        if (lane == 0) red[0] = r;
    }
    __syncthreads();
    return red[0];
}

// ---------------- fp32 -> fp16 conversion ----------------
__global__ __launch_bounds__(256) void k_f2h(const float* __restrict__ in,
                                             __half* __restrict__ out, int n4)
{
    for (int i = blockIdx.x * 256 + threadIdx.x; i < n4; i += gridDim.x * 256) {
        float4 v = *(const float4*)(in + (size_t)i * 4);
        __half2* o = (__half2*)(out + (size_t)i * 4);
        o[0] = __floats2half2_rn(v.x, v.y);
        o[1] = __floats2half2_rn(v.z, v.w);
    }
}

// ---------------- layernorm (half output) ----------------
__global__ __launch_bounds__(256) void k_layernorm_h(
    const float* __restrict__ x, const float* __restrict__ g,
    const float* __restrict__ b, __half* __restrict__ out)
{
    int t = blockIdx.x;
    const float* xr = x + (size_t)t * D;
    float s = 0.f, s2 = 0.f;
    for (int i = threadIdx.x; i < D; i += 256) {
        float v = xr[i];
        s += v; s2 += v * v;
    }
    float tot = blockReduceSum(s);
    float tot2 = blockReduceSum(s2);
    float mean = tot * (1.f / D);
    float var = tot2 * (1.f / D) - mean * mean;
    float rstd = rsqrtf(var + LN_EPS);
    __half* orow = out + (size_t)t * D;
    for (int i = threadIdx.x; i < D; i += 256) {
        orow[i] = __float2half((xr[i] - mean) * rstd * g[i] + b[i]);
    }
}

// ---------------- FP16 GEMM NT, cp.async 3-stage ----------------
// C[m,n] = sum_k A[m,k]*B[n,k] (+bias)(gelu)(+res)(tf32-round); A,B half.
// BM=BN=128, BK=32 halves, 8 warps (2m x 4n), warp tile 64x32, pitch 40 halves.
#define HT_PITCH 40
#define HT_STAGE (128 * HT_PITCH)   // halves
template<bool GELU, bool HASBIAS, bool HASRES, bool ROUND, bool HALFOUT>
__global__ __launch_bounds__(256) void k_hgemm_nt(
    const __half* __restrict__ A, int lda,
    const __half* __restrict__ B, int ldb,
    void* __restrict__ Cv, int ldc,
    int K,
    const float* __restrict__ bias,
    const float* __restrict__ res, int ldres)
{
    int m0 = blockIdx.y * 128, n0 = blockIdx.x * 128;
    A += (size_t)m0 * lda;
    B += (size_t)n0 * ldb;

    extern __shared__ __half smh[];
    __half* Abuf = smh;                 // [3][128][40]
    __half* Bbuf = smh + 3 * HT_STAGE;  // [3][128][40]

    int tid = threadIdx.x, lane = tid & 31, warp = tid >> 5;
    int wm = (warp & 1) * 64, wn = (warp >> 1) * 32;
    int lr = tid >> 1, lc = (tid & 1) * 8;   // row 0..127, col 0 or 8 halves (+16 second)

    float acc[4][4][4] = {};

    auto load = [&](int st, int k0) {
        __half* As_ = Abuf + st * HT_STAGE;
        __half* Bs_ = Bbuf + st * HT_STAGE;
        cp16(As_ + lr * HT_PITCH + lc,      A + (size_t)lr * lda + k0 + lc);
        cp16(As_ + lr * HT_PITCH + lc + 16, A + (size_t)lr * lda + k0 + lc + 16);
        cp16(Bs_ + lr * HT_PITCH + lc,      B + (size_t)lr * ldb + k0 + lc);
        cp16(Bs_ + lr * HT_PITCH + lc + 16, B + (size_t)lr * ldb + k0 + lc + 16);
    };

    int nk = K / 32;
    load(0, 0); cp_commit();
    load(1, 32); cp_commit();

    for (int i = 0; i < nk; i++) {
        if (i + 1 < nk) cp_wait<1>(); else cp_wait<0>();
        __syncthreads();
        if (i + 2 < nk) { load((i + 2) % 3, (i + 2) * 32); cp_commit(); }

        const __half* As_ = Abuf + (i % 3) * HT_STAGE;
        const __half* Bs_ = Bbuf + (i % 3) * HT_STAGE;
        #pragma unroll
        for (int ks = 0; ks < 2; ks++) {
            int kh = ks * 16 + (lane & 3) * 2;
            uint32_t af[4][4], bf[4][2];
            #pragma unroll
            for (int mf = 0; mf < 4; mf++) {
                int r = wm + mf * 16 + (lane >> 2);
                af[mf][0] = *(const uint32_t*)(As_ + r * HT_PITCH + kh);
                af[mf][1] = *(const uint32_t*)(As_ + (r + 8) * HT_PITCH + kh);
                af[mf][2] = *(const uint32_t*)(As_ + r * HT_PITCH + kh + 8);
                af[mf][3] = *(const uint32_t*)(As_ + (r + 8) * HT_PITCH + kh + 8);
            }
            #pragma unroll
            for (int nf = 0; nf < 4; nf++) {
                int n = wn + nf * 8 + (lane >> 2);
                bf[nf][0] = *(const uint32_t*)(Bs_ + n * HT_PITCH + kh);
                bf[nf][1] = *(const uint32_t*)(Bs_ + n * HT_PITCH + kh + 8);
            }
            #pragma unroll
            for (int mf = 0; mf < 4; mf++)
                #pragma unroll
                for (int nf = 0; nf < 4; nf++)
                    mma_f16(acc[mf][nf], af[mf], bf[nf]);
        }
        __syncthreads();
    }

    #pragma unroll
    for (int mf = 0; mf < 4; mf++) {
        int row = m0 + wm + mf * 16 + (lane >> 2);
        #pragma unroll
        for (int nf = 0; nf < 4; nf++) {
            int col = n0 + wn + nf * 8 + 2 * (lane & 3);
            #pragma unroll
            for (int half_ = 0; half_ < 2; half_++) {
                int r = row + half_ * 8;
                float v0 = acc[mf][nf][half_ * 2 + 0];
                float v1 = acc[mf][nf][half_ * 2 + 1];
                if (HASBIAS) { v0 += bias[col]; v1 += bias[col + 1]; }
                if (GELU) {
                    v0 = 0.5f * v0 * (1.f + erff(v0 * 0.70710678118654752f));
                    v1 = 0.5f * v1 * (1.f + erff(v1 * 0.70710678118654752f));
                }
                if (HASRES) {
                    v0 += res[(size_t)r * ldres + col];
                    v1 += res[(size_t)r * ldres + col + 1];
                }
                if (ROUND) {
                    v0 = __uint_as_float(f2tf(v0));
                    v1 = __uint_as_float(f2tf(v1));
                }
                if (HALFOUT) {
                    *(__half2*)((__half*)Cv + (size_t)r * ldc + col) = __floats2half2_rn(v0, v1);
                } else {
                    float2 o = {v0, v1};
                    *(float2*)((float*)Cv + (size_t)r * ldc + col) = o;
                }
            }
        }
    }
}

// ---------------- fused dual-softmax flash attention (tf32) ----------------
__global__ __launch_bounds__(256) void k_flash(
    const float* __restrict__ qkv, const float* __restrict__ logm,
    __half* __restrict__ cat)
{
    extern __shared__ float sm[];
    float* sQ = sm;             // [128][68]
    float* sK = sm + 8704;      // [2][64][68]
    float* sV = sm + 17408;     // [2][64][72]
    float* sM = sm + 26624;     // [2][128][68]

    int bid = blockIdx.x;
    int qi = 15 - (bid >> 4);   // heavy blocks first
    int h  = bid & 15;
    int q0 = qi * 128;
    int nkb = 2 * (qi + 1);

    int tid = threadIdx.x, lane = tid & 31, warp = tid >> 5;
    int p_ = lane >> 2, q_ = lane & 3;
    int wrow0 = warp * 16;

    #pragma unroll
    for (int i = 0; i < 8; i++) {
        int idx = tid + i * 256;
        int row = idx >> 4, c4 = (idx & 15) * 4;
        cp16(sQ + row * 68 + c4, qkv + (size_t)(q0 + row) * D3 + h * 64 + c4);
    }
    #pragma unroll
    for (int i = 0; i < 4; i++) {
        int idx = tid + i * 256;
        int row = idx >> 4, c4 = (idx & 15) * 4;
        cp16(sK + row * 68 + c4, qkv + (size_t)row * D3 + D + h * 64 + c4);
        cp16(sV + row * 72 + c4, qkv + (size_t)row * D3 + 2 * D + h * 64 + c4);
    }
    #pragma unroll
    for (int i = 0; i < 8; i++) {
        int idx = tid + i * 256;
        int row = idx >> 4, c4 = (idx & 15) * 4;
        cp16(sM + row * 68 + c4, logm + ((size_t)h * T + q0 + row) * T + c4);
    }
    cp_commit();

    float O1[8][4] = {}, O2[8][4] = {};
    float m1[2] = {-1e30f, -1e30f}, l1[2] = {0.f, 0.f};
    float m2[2] = {-1e30f, -1e30f}, l2[2] = {0.f, 0.f};

    int r0 = wrow0 + p_;
    int t0 = q0 + r0, t1 = t0 + 8;
    int srcA = (lane & ~3) | (q_ >> 1);
    int srcB = srcA + 2;
    bool odd = q_ & 1;

    for (int j = 0; j < nkb; j++) {
        int st = j & 1;
        int kb0 = j * 64;
        cp_wait<0>();
        __syncthreads();
        if (j + 1 < nkb) {
            int st2 = st ^ 1, kb2 = kb0 + 64;
            float* dK = sK + st2 * 4352;
            float* dV = sV + st2 * 4608;
            float* dM = sM + st2 * 8704;
            #pragma unroll
            for (int i = 0; i < 4; i++) {
                int idx = tid + i * 256;
                int row = idx >> 4, c4 = (idx & 15) * 4;
                cp16(dK + row * 68 + c4, qkv + (size_t)(kb2 + row) * D3 + D + h * 64 + c4);
                cp16(dV + row * 72 + c4, qkv + (size_t)(kb2 + row) * D3 + 2 * D + h * 64 + c4);
            }
            #pragma unroll
            for (int i = 0; i < 8; i++) {
                int idx = tid + i * 256;
                int row = idx >> 4, c4 = (idx & 15) * 4;
                cp16(dM + row * 68 + c4, logm + ((size_t)h * T + q0 + row) * T + kb2 + c4);
            }
            cp_commit();
        }

        if (kb0 > q0 + wrow0 + 15) continue;

        const float* sK_ = sK + st * 4352;
        const float* sV_ = sV + st * 4608;
        const float* sM_ = sM + st * 8704;

        float sg[8][4];
        #pragma unroll
        for (int nf = 0; nf < 8; nf++) {
            int c0 = nf * 8 + 2 * q_;
            float2 a = *(const float2*)(sM_ + r0 * 68 + c0);
            float2 b = *(const float2*)(sM_ + (r0 + 8) * 68 + c0);
            sg[nf][0] = sigf(a.x); sg[nf][1] = sigf(a.y);
            sg[nf][2] = sigf(b.x); sg[nf][3] = sigf(b.y);
        }

        float sc[8][4] = {};
        #pragma unroll
        for (int kc = 0; kc < 8; kc++) {
            int kb = kc * 8 + q_;
            uint32_t af[4];
            af[0] = __float_as_uint(sQ[r0 * 68 + kb]);
            af[1] = __float_as_uint(sQ[(r0 + 8) * 68 + kb]);
            af[2] = __float_as_uint(sQ[r0 * 68 + kb + 4]);
            af[3] = __float_as_uint(sQ[(r0 + 8) * 68 + kb + 4]);
            #pragma unroll
            for (int nf = 0; nf < 8; nf++) {
                uint32_t bf[2];
                bf[0] = __float_as_uint(sK_[(nf * 8 + p_) * 68 + kb]);
                bf[1] = __float_as_uint(sK_[(nf * 8 + p_) * 68 + kb + 4]);
                mma_tf32(sc[nf], af, bf);
            }
        }
        #pragma unroll
        for (int nf = 0; nf < 8; nf++) {
            sc[nf][0] *= 0.125f; sc[nf][1] *= 0.125f;
            sc[nf][2] *= 0.125f; sc[nf][3] *= 0.125f;
        }

        #pragma unroll
        for (int br = 0; br < 2; br++) {
            float* mB = br ? m2 : m1;
            float* lB = br ? l2 : l1;
            float (*OB)[4] = br ? O2 : O1;

            float v[8][4];
            float rmx0 = -1e30f, rmx1 = -1e30f;
            #pragma unroll
            for (int nf = 0; nf < 8; nf++) {
                int c0 = kb0 + nf * 8 + 2 * q_;
                float w0 = br ? sc[nf][0] * sg[nf][0] : sc[nf][0];
                float w1 = br ? sc[nf][1] * sg[nf][1] : sc[nf][1];
                float w2 = br ? sc[nf][2] * sg[nf][2] : sc[nf][2];
                float w3 = br ? sc[nf][3] * sg[nf][3] : sc[nf][3];
                v[nf][0] = (c0     <= t0) ? w0 : -1e30f;
                v[nf][1] = (c0 + 1 <= t0) ? w1 : -1e30f;
                v[nf][2] = (c0     <= t1) ? w2 : -1e30f;
                v[nf][3] = (c0 + 1 <= t1) ? w3 : -1e30f;
                rmx0 = fmaxf(rmx0, fmaxf(v[nf][0], v[nf][1]));
                rmx1 = fmaxf(rmx1, fmaxf(v[nf][2], v[nf][3]));
            }
            rmx0 = fmaxf(rmx0, __shfl_xor_sync(0xffffffff, rmx0, 1));
            rmx0 = fmaxf(rmx0, __shfl_xor_sync(0xffffffff, rmx0, 2));
            rmx1 = fmaxf(rmx1, __shfl_xor_sync(0xffffffff, rmx1, 1));
            rmx1 = fmaxf(rmx1, __shfl_xor_sync(0xffffffff, rmx1, 2));

            float mn0 = fmaxf(mB[0], rmx0), mn1 = fmaxf(mB[1], rmx1);
            float al0 = __expf(mB[0] - mn0), al1 = __expf(mB[1] - mn1);
            float rs0 = 0.f, rs1 = 0.f;
            #pragma unroll
            for (int nf = 0; nf < 8; nf++) {
                v[nf][0] = __expf(v[nf][0] - mn0);
                v[nf][1] = __expf(v[nf][1] - mn0);
                v[nf][2] = __expf(v[nf][2] - mn1);
                v[nf][3] = __expf(v[nf][3] - mn1);
                rs0 += v[nf][0] + v[nf][1];
                rs1 += v[nf][2] + v[nf][3];
            }
            rs0 += __shfl_xor_sync(0xffffffff, rs0, 1);
            rs0 += __shfl_xor_sync(0xffffffff, rs0, 2);
            rs1 += __shfl_xor_sync(0xffffffff, rs1, 1);
            rs1 += __shfl_xor_sync(0xffffffff, rs1, 2);
            lB[0] = lB[0] * al0 + rs0; lB[1] = lB[1] * al1 + rs1;
            mB[0] = mn0; mB[1] = mn1;

            #pragma unroll
            for (int nf = 0; nf < 8; nf++) {
                OB[nf][0] *= al0; OB[nf][1] *= al0;
                OB[nf][2] *= al1; OB[nf][3] *= al1;
                v[nf][0] = __uint_as_float(f2tf(v[nf][0]));
                v[nf][1] = __uint_as_float(f2tf(v[nf][1]));
                v[nf][2] = __uint_as_float(f2tf(v[nf][2]));
                v[nf][3] = __uint_as_float(f2tf(v[nf][3]));
            }

            #pragma unroll
            for (int kc = 0; kc < 8; kc++) {
                float x0 = __shfl_sync(0xffffffff, v[kc][0], srcA);
                float x1 = __shfl_sync(0xffffffff, v[kc][1], srcA);
                float x2 = __shfl_sync(0xffffffff, v[kc][2], srcA);
                float x3 = __shfl_sync(0xffffffff, v[kc][3], srcA);
                float y0 = __shfl_sync(0xffffffff, v[kc][0], srcB);
                float y1 = __shfl_sync(0xffffffff, v[kc][1], srcB);
                float y2 = __shfl_sync(0xffffffff, v[kc][2], srcB);
                float y3 = __shfl_sync(0xffffffff, v[kc][3], srcB);
                uint32_t a[4];
                a[0] = __float_as_uint(odd ? x1 : x0);
                a[1] = __float_as_uint(odd ? x3 : x2);
                a[2] = __float_as_uint(odd ? y1 : y0);
                a[3] = __float_as_uint(odd ? y3 : y2);
                #pragma unroll
                for (int nf = 0; nf < 8; nf++) {
                    uint32_t bf[2];
                    bf[0] = __float_as_uint(sV_[(kc * 8 + q_) * 72 + nf * 8 + p_]);
                    bf[1] = __float_as_uint(sV_[(kc * 8 + q_ + 4) * 72 + nf * 8 + p_]);
                    mma_tf32(OB[nf], a, bf);
                }
            }
        }
    }

    float rl10 = 1.f / l1[0], rl11 = 1.f / l1[1];
    float rl20 = 1.f / l2[0], rl21 = 1.f / l2[1];
    int row = q0 + wrow0 + p_;
    #pragma unroll
    for (int nf = 0; nf < 8; nf++) {
        int col = h * 64 + nf * 8 + 2 * q_;
        *(__half2*)(cat + (size_t)row * D2 + col)       = __floats2half2_rn(O1[nf][0] * rl10, O1[nf][1] * rl10);
        *(__half2*)(cat + (size_t)(row + 8) * D2 + col) = __floats2half2_rn(O1[nf][2] * rl11, O1[nf][3] * rl11);
        *(__half2*)(cat + (size_t)row * D2 + D + col)       = __floats2half2_rn(O2[nf][0] * rl20, O2[nf][1] * rl20);
        *(__half2*)(cat + (size_t)(row + 8) * D2 + D + col) = __floats2half2_rn(O2[nf][2] * rl21, O2[nf][3] * rl21);
    }
}

// ---------------- sigmoid mean (flat, full-chip) ----------------
__global__ __launch_bounds__(256) void k_sigsum(const float* __restrict__ lm)
{
    const size_t n4 = (size_t)H * T * T / 4;
    const float4* p = (const float4*)lm;
    float s = 0.f;
    for (size_t i = (size_t)blockIdx.x * 256 + threadIdx.x; i < n4;
         i += (size_t)gridDim.x * 256) {
        float4 v = p[i];
        s += sigf(v.x) + sigf(v.y) + sigf(v.z) + sigf(v.w);
    }
    float tot = blockReduceSum(s);
    if (threadIdx.x == 0) atomicAdd(&g_sigacc, (double)tot);
}

__global__ void k_zero_acc() { g_sigacc = 0.0; }

__global__ void k_write_sp(float* out, int out_size)
{
    const long long TD = (long long)T * D;
    if (out_size > TD) {
        double mean = g_sigacc / ((double)H * (double)T * (double)T);
        out[TD] = (float)(SPARSITY_LAMBDA * mean);
    }
}

// ---------------- launch ----------------
#define HT_SMEM (6 * HT_STAGE * sizeof(__half))  // 61440
#define FL_SMEM (44032 * sizeof(float))          // 176128

extern "C" void kernel_launch(void* const* d_in, const int* in_sizes, int n_in,
                              void* d_out, int out_size)
{
    const float* x      = (const float*)d_in[0];
    const float* W_qkv  = (const float*)d_in[2];
    const float* W_out  = (const float*)d_in[3];
    const float* logm   = (const float*)d_in[4];
    const float* W_gate = (const float*)d_in[5];
    const float* b_gate = (const float*)d_in[6];
    const float* g1     = (const float*)d_in[7];
    const float* b1     = (const float*)d_in[8];
    const float* g2     = (const float*)d_in[9];
    const float* b2     = (const float*)d_in[10];
    const float* W_ff1  = (const float*)d_in[11];
    const float* b_ff1  = (const float*)d_in[12];
    const float* W_ff2  = (const float*)d_in[13];
    const float* b_ff2  = (const float*)d_in[14];
    float* out = (float*)d_out;

    __half *xnh, *cath, *tmph, *hnh, *ffh;
    __half *wqkvh, *wgateh, *wouth, *wff1h, *wff2h;
    float *qkv, *hbuf;
    cudaGetSymbolAddress((void**)&xnh,   g_xnh);
    cudaGetSymbolAddress((void**)&qkv,   g_qkv);
    cudaGetSymbolAddress((void**)&cath,  g_cath);
    cudaGetSymbolAddress((void**)&tmph,  g_tmph);
    cudaGetSymbolAddress((void**)&hbuf,  g_h);
    cudaGetSymbolAddress((void**)&hnh,   g_hnh);
    cudaGetSymbolAddress((void**)&ffh,   g_ffh);
    cudaGetSymbolAddress((void**)&wqkvh, g_wqkvh);
    cudaGetSymbolAddress((void**)&wgateh, g_wgateh);
    cudaGetSymbolAddress((void**)&wouth, g_wouth);
    cudaGetSymbolAddress((void**)&wff1h, g_wff1h);
    cudaGetSymbolAddress((void**)&wff2h, g_wff2h);

    cudaFuncSetAttribute(k_hgemm_nt<false, false, false, true,  false>, cudaFuncAttributeMaxDynamicSharedMemorySize, HT_SMEM);
    cudaFuncSetAttribute(k_hgemm_nt<false, true,  false, false, true >, cudaFuncAttributeMaxDynamicSharedMemorySize, HT_SMEM);
    cudaFuncSetAttribute(k_hgemm_nt<false, false, true,  false, false>, cudaFuncAttributeMaxDynamicSharedMemorySize, HT_SMEM);
    cudaFuncSetAttribute(k_hgemm_nt<true,  true,  false, false, true >, cudaFuncAttributeMaxDynamicSharedMemorySize, HT_SMEM);
    cudaFuncSetAttribute(k_hgemm_nt<false, true,  true,  false, false>, cudaFuncAttributeMaxDynamicSharedMemorySize, HT_SMEM);
    cudaFuncSetAttribute(k_flash, cudaFuncAttributeMaxDynamicSharedMemorySize, FL_SMEM);

    k_zero_acc<<<1, 1>>>();

    // weight conversions (fp32 -> fp16)
    k_f2h<<<1184, 256>>>(W_qkv,  wqkvh,  D3 * D / 4);
    k_f2h<<<1184, 256>>>(W_gate, wgateh, D * D2 / 4);
    k_f2h<<<1184, 256>>>(W_out,  wouth,  D * D / 4);
    k_f2h<<<1184, 256>>>(W_ff1,  wff1h,  DFF * D / 4);
    k_f2h<<<1184, 256>>>(W_ff2,  wff2h,  D * DFF / 4);

    // ln1 -> half
    k_layernorm_h<<<T, 256>>>(x, g1, b1, xnh);

    // qkv = xn @ W_qkv^T (fp16 in, fp32+tf32-round out)
    k_hgemm_nt<false, false, false, true, false><<<dim3(D3 / 128, T / 128), 256, HT_SMEM>>>(
        xnh, D, wqkvh, D, qkv, D3, D, nullptr, nullptr, 0);

    // sigmoid-mean over the full mask
    k_sigsum<<<1184, 256>>>(logm);

    // fused dual-softmax attention -> cat (half)
    k_flash<<<256, 256, FL_SMEM>>>(qkv, logm, cath);

    // tmp = cat @ W_gate^T + b_gate  (half out)
    k_hgemm_nt<false, true, false, false, true><<<dim3(D / 128, T / 128), 256, HT_SMEM>>>(
        cath, D2, wgateh, D2, tmph, D, D2, b_gate, nullptr, 0);

    // h = x + tmp @ W_out^T  (fp32 out)
    k_hgemm_nt<false, false, true, false, false><<<dim3(D / 128, T / 128), 256, HT_SMEM>>>(
        tmph, D, wouth, D, hbuf, D, D, nullptr, x, D);

    // ln2 -> half
    k_layernorm_h<<<T, 256>>>(hbuf, g2, b2, hnh);

    // ff = gelu(hn @ W_ff1^T + b_ff1)  (half out)
    k_hgemm_nt<true, true, false, false, true><<<dim3(DFF / 128, T / 128), 256, HT_SMEM>>>(
        hnh, D, wff1h, D, ffh, DFF, D, b_ff1, nullptr, 0);

    // out = h + ff @ W_ff2^T + b_ff2  (fp32 out)
    k_hgemm_nt<false, true, true, false, false><<<dim3(D / 128, T / 128), 256, HT_SMEM>>>(
        ffh, DFF, wff2h, DFF, out, D, DFF, b_ff2, hbuf, D);

    k_write_sp<<<1, 1>>>(out, out_size);
}

// round 8
// speedup vs baseline: 4.6365x; 1.0696x over previous
#include <cuda_runtime.h>
#include <cuda_fp16.h>
#include <math_constants.h>
#include <cstdint>

#define T 2048
#define D 1024
#define H 16
#define DH 64
#define D3 3072
#define D2 2048
#define DFF 4096
#define LN_EPS 1e-5f
#define SPARSITY_LAMBDA 0.0005f

// ---------------- scratch ----------------
__device__ __half g_xnh[(size_t)T * D];
__device__ __half g_qkvh[(size_t)T * D3];
__device__ __half g_cath[(size_t)T * D2];
__device__ __half g_tmph[(size_t)T * D];
__device__ float  g_h[(size_t)T * D];
__device__ __half g_hnh[(size_t)T * D];
__device__ __half g_ffh[(size_t)T * DFF];
__device__ __half g_wqkvh[(size_t)D3 * D];
__device__ __half g_wgateh[(size_t)D * D2];
__device__ __half g_wouth[(size_t)D * D];
__device__ __half g_wff1h[(size_t)DFF * D];
__device__ __half g_wff2h[(size_t)D * DFF];
__device__ double g_sigacc;

// ---------------- helpers ----------------
__device__ __forceinline__ void mma_f16(float (&d)[4], const uint32_t (&a)[4], const uint32_t (&b)[2]) {
    asm volatile(
        "mma.sync.aligned.m16n8k16.row.col.f32.f16.f16.f32 "
        "{%0,%1,%2,%3}, {%4,%5,%6,%7}, {%8,%9}, {%0,%1,%2,%3};\n"
        : "+f"(d[0]), "+f"(d[1]), "+f"(d[2]), "+f"(d[3])
        : "r"(a[0]), "r"(a[1]), "r"(a[2]), "r"(a[3]), "r"(b[0]), "r"(b[1]));
}

__device__ __forceinline__ void cp16(void* sdst, const void* gsrc) {
    uint32_t s = (uint32_t)__cvta_generic_to_shared(sdst);
    asm volatile("cp.async.cg.shared.global [%0], [%1], 16;" :: "r"(s), "l"(gsrc));
}
__device__ __forceinline__ void cp_commit() { asm volatile("cp.async.commit_group;"); }
template<int N> __device__ __forceinline__ void cp_wait() {
    asm volatile("cp.async.wait_group %0;" :: "n"(N));
}

__device__ __forceinline__ float sigf(float x) { return 1.f / (1.f + __expf(-x)); }

__device__ __forceinline__ float blockReduceSum(float v) {
    __shared__ float red[32];
    int lane = threadIdx.x & 31, wid = threadIdx.x >> 5;
    #pragma unroll
    for (int o = 16; o > 0; o >>= 1) v += __shfl_xor_sync(0xffffffff, v, o);
    __syncthreads();
    if (lane == 0) red[wid] = v;
    __syncthreads();
    int nw = (blockDim.x + 31) >> 5;
    float r = (threadIdx.x < nw) ? red[threadIdx.x] : 0.f;
    if (wid == 0) {
        #pragma unroll
        for (int o = 16; o > 0; o >>= 1) r += __shfl_xor_sync(0xffffffff, r, o);
        if (lane == 0) red[0] = r;
    }
    __syncthreads();
    return red[0];
}

// ---------------- fp32 -> fp16 conversion ----------------
__global__ __launch_bounds__(256) void k_f2h(const float* __restrict__ in,
                                             __half* __restrict__ out, int n4)
{
    for (int i = blockIdx.x * 256 + threadIdx.x; i < n4; i += gridDim.x * 256) {
        float4 v = *(const float4*)(in + (size_t)i * 4);
        __half2* o = (__half2*)(out + (size_t)i * 4);
        o[0] = __floats2half2_rn(v.x, v.y);
        o[1] = __floats2half2_rn(v.z, v.w);
    }
}

// ---------------- layernorm (half output) ----------------
__global__ __launch_bounds__(256) void k_layernorm_h(
    const float* __restrict__ x, const float* __restrict__ g,
    const float* __restrict__ b, __half* __restrict__ out)
{
    int t = blockIdx.x;
    const float* xr = x + (size_t)t * D;
    float s = 0.f, s2 = 0.f;
    for (int i = threadIdx.x; i < D; i += 256) {
        float v = xr[i];
        s += v; s2 += v * v;
    }
    float tot = blockReduceSum(s);
    float tot2 = blockReduceSum(s2);
    float mean = tot * (1.f / D);
    float var = tot2 * (1.f / D) - mean * mean;
    float rstd = rsqrtf(var + LN_EPS);
    __half* orow = out + (size_t)t * D;
    for (int i = threadIdx.x; i < D; i += 256) {
        orow[i] = __float2half((xr[i] - mean) * rstd * g[i] + b[i]);
    }
}

// ---------------- FP16 GEMM NT, cp.async 3-stage ----------------
#define HT_PITCH 40
#define HT_STAGE (128 * HT_PITCH)
template<bool GELU, bool HASBIAS, bool HASRES, bool HALFOUT>
__global__ __launch_bounds__(256) void k_hgemm_nt(
    const __half* __restrict__ A, int lda,
    const __half* __restrict__ B, int ldb,
    void* __restrict__ Cv, int ldc,
    int K,
    const float* __restrict__ bias,
    const float* __restrict__ res, int ldres)
{
    int m0 = blockIdx.y * 128, n0 = blockIdx.x * 128;
    A += (size_t)m0 * lda;
    B += (size_t)n0 * ldb;

    extern __shared__ __half smh[];
    __half* Abuf = smh;
    __half* Bbuf = smh + 3 * HT_STAGE;

    int tid = threadIdx.x, lane = tid & 31, warp = tid >> 5;
    int wm = (warp & 1) * 64, wn = (warp >> 1) * 32;
    int lr = tid >> 1, lc = (tid & 1) * 8;

    float acc[4][4][4] = {};

    auto load = [&](int st, int k0) {
        __half* As_ = Abuf + st * HT_STAGE;
        __half* Bs_ = Bbuf + st * HT_STAGE;
        cp16(As_ + lr * HT_PITCH + lc,      A + (size_t)lr * lda + k0 + lc);
        cp16(As_ + lr * HT_PITCH + lc + 16, A + (size_t)lr * lda + k0 + lc + 16);
        cp16(Bs_ + lr * HT_PITCH + lc,      B + (size_t)lr * ldb + k0 + lc);
        cp16(Bs_ + lr * HT_PITCH + lc + 16, B + (size_t)lr * ldb + k0 + lc + 16);
    };

    int nk = K / 32;
    load(0, 0); cp_commit();
    load(1, 32); cp_commit();

    for (int i = 0; i < nk; i++) {
        if (i + 1 < nk) cp_wait<1>(); else cp_wait<0>();
        __syncthreads();
        if (i + 2 < nk) { load((i + 2) % 3, (i + 2) * 32); cp_commit(); }

        const __half* As_ = Abuf + (i % 3) * HT_STAGE;
        const __half* Bs_ = Bbuf + (i % 3) * HT_STAGE;
        #pragma unroll
        for (int ks = 0; ks < 2; ks++) {
            int kh = ks * 16 + (lane & 3) * 2;
            uint32_t af[4][4], bf[4][2];
            #pragma unroll
            for (int mf = 0; mf < 4; mf++) {
                int r = wm + mf * 16 + (lane >> 2);
                af[mf][0] = *(const uint32_t*)(As_ + r * HT_PITCH + kh);
                af[mf][1] = *(const uint32_t*)(As_ + (r + 8) * HT_PITCH + kh);
                af[mf][2] = *(const uint32_t*)(As_ + r * HT_PITCH + kh + 8);
                af[mf][3] = *(const uint32_t*)(As_ + (r + 8) * HT_PITCH + kh + 8);
            }
            #pragma unroll
            for (int nf = 0; nf < 4; nf++) {
                int n = wn + nf * 8 + (lane >> 2);
                bf[nf][0] = *(const uint32_t*)(Bs_ + n * HT_PITCH + kh);
                bf[nf][1] = *(const uint32_t*)(Bs_ + n * HT_PITCH + kh + 8);
            }
            #pragma unroll
            for (int mf = 0; mf < 4; mf++)
                #pragma unroll
                for (int nf = 0; nf < 4; nf++)
                    mma_f16(acc[mf][nf], af[mf], bf[nf]);
        }
        __syncthreads();
    }

    #pragma unroll
    for (int mf = 0; mf < 4; mf++) {
        int row = m0 + wm + mf * 16 + (lane >> 2);
        #pragma unroll
        for (int nf = 0; nf < 4; nf++) {
            int col = n0 + wn + nf * 8 + 2 * (lane & 3);
            #pragma unroll
            for (int half_ = 0; half_ < 2; half_++) {
                int r = row + half_ * 8;
                float v0 = acc[mf][nf][half_ * 2 + 0];
                float v1 = acc[mf][nf][half_ * 2 + 1];
                if (HASBIAS) { v0 += bias[col]; v1 += bias[col + 1]; }
                if (GELU) {
                    v0 = 0.5f * v0 * (1.f + erff(v0 * 0.70710678118654752f));
                    v1 = 0.5f * v1 * (1.f + erff(v1 * 0.70710678118654752f));
                }
                if (HASRES) {
                    v0 += res[(size_t)r * ldres + col];
                    v1 += res[(size_t)r * ldres + col + 1];
                }
                if (HALFOUT) {
                    *(__half2*)((__half*)Cv + (size_t)r * ldc + col) = __floats2half2_rn(v0, v1);
                } else {
                    float2 o = {v0, v1};
                    *(float2*)((float*)Cv + (size_t)r * ldc + col) = o;
                }
            }
        }
    }
}

// ---------------- fused dual-softmax flash attention (fp16 MMA) ----------------
// smem layout (bytes):
//   sQh  [128][72]h           @ 0        18432
//   sKh  [2][64][72]h         @ 18432    18432
//   sVn  [2][64][72]h         @ 36864    18432
//   sVt  [2][64][72]h         @ 55296    18432
//   sP   [2][8][16][72]h      @ 73728    36864
//   sM   [2][128][68]f        @ 110592   69632   -> total 180224
__global__ __launch_bounds__(256) void k_flash(
    const __half* __restrict__ qkv, const float* __restrict__ logm,
    __half* __restrict__ cat)
{
    extern __shared__ char smraw[];
    __half* sQh = (__half*)smraw;
    __half* sKh = (__half*)(smraw + 18432);
    __half* sVn = (__half*)(smraw + 36864);
    __half* sVt = (__half*)(smraw + 55296);
    __half* sP  = (__half*)(smraw + 73728);
    float*  sM  = (float*)(smraw + 110592);

    int bid = blockIdx.x;
    int qi = 15 - (bid >> 4);   // heavy blocks first
    int h  = bid & 15;
    int q0 = qi * 128;
    int nkb = 2 * (qi + 1);

    int tid = threadIdx.x, lane = tid & 31, warp = tid >> 5;
    int p_ = lane >> 2, q_ = lane & 3;
    int wrow0 = warp * 16;

    // stage-0 loads
    #pragma unroll
    for (int i = 0; i < 4; i++) {
        int idx = tid + i * 256;
        int row = idx >> 3, ch = (idx & 7) * 8;
        cp16(sQh + row * 72 + ch, qkv + (size_t)(q0 + row) * D3 + h * 64 + ch);
    }
    #pragma unroll
    for (int i = 0; i < 2; i++) {
        int idx = tid + i * 256;
        int row = idx >> 3, ch = (idx & 7) * 8;
        cp16(sKh + row * 72 + ch, qkv + (size_t)row * D3 + D + h * 64 + ch);
        cp16(sVn + row * 72 + ch, qkv + (size_t)row * D3 + 2 * D + h * 64 + ch);
    }
    #pragma unroll
    for (int i = 0; i < 8; i++) {
        int idx = tid + i * 256;
        int row = idx >> 4, c4 = (idx & 15) * 4;
        cp16(sM + row * 68 + c4, logm + ((size_t)h * T + q0 + row) * T + c4);
    }
    cp_commit();

    float O1[8][4] = {}, O2[8][4] = {};
    float m1[2] = {-1e30f, -1e30f}, l1[2] = {0.f, 0.f};
    float m2[2] = {-1e30f, -1e30f}, l2[2] = {0.f, 0.f};

    int r0 = wrow0 + p_;
    int t0 = q0 + r0, t1 = t0 + 8;
    __half* sP1 = sP + warp * 1152;           // branch-0 P tile for this warp
    __half* sP2 = sP + 9216 + warp * 1152;    // branch-1

    int vdh = tid & 63;              // transpose role
    int vtb = (tid >> 6) * 16;

    for (int j = 0; j < nkb; j++) {
        int st = j & 1;
        int kb0 = j * 64;
        cp_wait<0>();
        __syncthreads();
        if (j + 1 < nkb) {
            int st2 = st ^ 1, kb2 = kb0 + 64;
            __half* dK = sKh + st2 * 4608;
            __half* dV = sVn + st2 * 4608;
            float*  dM = sM  + st2 * 8704;
            #pragma unroll
            for (int i = 0; i < 2; i++) {
                int idx = tid + i * 256;
                int row = idx >> 3, ch = (idx & 7) * 8;
                cp16(dK + row * 72 + ch, qkv + (size_t)(kb2 + row) * D3 + D + h * 64 + ch);
                cp16(dV + row * 72 + ch, qkv + (size_t)(kb2 + row) * D3 + 2 * D + h * 64 + ch);
            }
            #pragma unroll
            for (int i = 0; i < 8; i++) {
                int idx = tid + i * 256;
                int row = idx >> 4, c4 = (idx & 15) * 4;
                cp16(dM + row * 68 + c4, logm + ((size_t)h * T + q0 + row) * T + kb2 + c4);
            }
            cp_commit();
        }

        const __half* sKs = sKh + st * 4608;
        const __half* sVns = sVn + st * 4608;
        __half* sVts = sVt + st * 4608;
        const float* sMs = sM + st * 8704;

        // transpose V: sVt[dh][tok] = V[tok][dh]  (all threads, then barrier)
        #pragma unroll
        for (int t2 = 0; t2 < 16; t2 += 2) {
            int tok = vtb + t2;
            __half a = sVns[tok * 72 + vdh];
            __half b = sVns[(tok + 1) * 72 + vdh];
            *(__half2*)(sVts + vdh * 72 + tok) = __halves2half2(a, b);
        }
        __syncthreads();

        if (kb0 > q0 + wrow0 + 15) continue;   // this warp fully above diagonal

        // sigmoid tile
        float sg[8][4];
        #pragma unroll
        for (int nf = 0; nf < 8; nf++) {
            int c0 = nf * 8 + 2 * q_;
            float2 a = *(const float2*)(sMs + r0 * 68 + c0);
            float2 b = *(const float2*)(sMs + (r0 + 8) * 68 + c0);
            sg[nf][0] = sigf(a.x); sg[nf][1] = sigf(a.y);
            sg[nf][2] = sigf(b.x); sg[nf][3] = sigf(b.y);
        }

        // S = Q K^T / 8  (fp16 mma, k16 x 4 steps)
        float sc[8][4] = {};
        #pragma unroll
        for (int kc = 0; kc < 4; kc++) {
            int kh = kc * 16 + 2 * q_;
            uint32_t af[4];
            af[0] = *(const uint32_t*)(sQh + r0 * 72 + kh);
            af[1] = *(const uint32_t*)(sQh + (r0 + 8) * 72 + kh);
            af[2] = *(const uint32_t*)(sQh + r0 * 72 + kh + 8);
            af[3] = *(const uint32_t*)(sQh + (r0 + 8) * 72 + kh + 8);
            #pragma unroll
            for (int nf = 0; nf < 8; nf++) {
                uint32_t bf[2];
                bf[0] = *(const uint32_t*)(sKs + (nf * 8 + p_) * 72 + kh);
                bf[1] = *(const uint32_t*)(sKs + (nf * 8 + p_) * 72 + kh + 8);
                mma_f16(sc[nf], af, bf);
            }
        }
        #pragma unroll
        for (int nf = 0; nf < 8; nf++) {
            sc[nf][0] *= 0.125f; sc[nf][1] *= 0.125f;
            sc[nf][2] *= 0.125f; sc[nf][3] *= 0.125f;
        }

        // two online-softmax branches -> P staged to smem as half
        #pragma unroll
        for (int br = 0; br < 2; br++) {
            float* mB = br ? m2 : m1;
            float* lB = br ? l2 : l1;
            float (*OB)[4] = br ? O2 : O1;
            __half* sPw = br ? sP2 : sP1;

            float v[8][4];
            float rmx0 = -1e30f, rmx1 = -1e30f;
            #pragma unroll
            for (int nf = 0; nf < 8; nf++) {
                int c0 = kb0 + nf * 8 + 2 * q_;
                float w0 = br ? sc[nf][0] * sg[nf][0] : sc[nf][0];
                float w1 = br ? sc[nf][1] * sg[nf][1] : sc[nf][1];
                float w2 = br ? sc[nf][2] * sg[nf][2] : sc[nf][2];
                float w3 = br ? sc[nf][3] * sg[nf][3] : sc[nf][3];
                v[nf][0] = (c0     <= t0) ? w0 : -1e30f;
                v[nf][1] = (c0 + 1 <= t0) ? w1 : -1e30f;
                v[nf][2] = (c0     <= t1) ? w2 : -1e30f;
                v[nf][3] = (c0 + 1 <= t1) ? w3 : -1e30f;
                rmx0 = fmaxf(rmx0, fmaxf(v[nf][0], v[nf][1]));
                rmx1 = fmaxf(rmx1, fmaxf(v[nf][2], v[nf][3]));
            }
            rmx0 = fmaxf(rmx0, __shfl_xor_sync(0xffffffff, rmx0, 1));
            rmx0 = fmaxf(rmx0, __shfl_xor_sync(0xffffffff, rmx0, 2));
            rmx1 = fmaxf(rmx1, __shfl_xor_sync(0xffffffff, rmx1, 1));
            rmx1 = fmaxf(rmx1, __shfl_xor_sync(0xffffffff, rmx1, 2));

            float mn0 = fmaxf(mB[0], rmx0), mn1 = fmaxf(mB[1], rmx1);
            float al0 = __expf(mB[0] - mn0), al1 = __expf(mB[1] - mn1);
            float rs0 = 0.f, rs1 = 0.f;
            #pragma unroll
            for (int nf = 0; nf < 8; nf++) {
                v[nf][0] = __expf(v[nf][0] - mn0);
                v[nf][1] = __expf(v[nf][1] - mn0);
                v[nf][2] = __expf(v[nf][2] - mn1);
                v[nf][3] = __expf(v[nf][3] - mn1);
                rs0 += v[nf][0] + v[nf][1];
                rs1 += v[nf][2] + v[nf][3];
            }
            rs0 += __shfl_xor_sync(0xffffffff, rs0, 1);
            rs0 += __shfl_xor_sync(0xffffffff, rs0, 2);
            rs1 += __shfl_xor_sync(0xffffffff, rs1, 1);
            rs1 += __shfl_xor_sync(0xffffffff, rs1, 2);
            lB[0] = lB[0] * al0 + rs0; lB[1] = lB[1] * al1 + rs1;
            mB[0] = mn0; mB[1] = mn1;

            #pragma unroll
            for (int nf = 0; nf < 8; nf++) {
                OB[nf][0] *= al0; OB[nf][1] *= al0;
                OB[nf][2] *= al1; OB[nf][3] *= al1;
                // stage P as half: rows p_ / p_+8, cols nf*8+2q_
                *(__half2*)(sPw + p_ * 72 + nf * 8 + 2 * q_)       = __floats2half2_rn(v[nf][0], v[nf][1]);
                *(__half2*)(sPw + (p_ + 8) * 72 + nf * 8 + 2 * q_) = __floats2half2_rn(v[nf][2], v[nf][3]);
            }
        }
        __syncwarp();

        // P @ V for both branches (fp16 mma, V from transposed tile)
        #pragma unroll
        for (int kc = 0; kc < 4; kc++) {
            int kh = kc * 16 + 2 * q_;
            uint32_t a1f[4], a2f[4];
            a1f[0] = *(const uint32_t*)(sP1 + p_ * 72 + kh);
            a1f[1] = *(const uint32_t*)(sP1 + (p_ + 8) * 72 + kh);
            a1f[2] = *(const uint32_t*)(sP1 + p_ * 72 + kh + 8);
            a1f[3] = *(const uint32_t*)(sP1 + (p_ + 8) * 72 + kh + 8);
            a2f[0] = *(const uint32_t*)(sP2 + p_ * 72 + kh);
            a2f[1] = *(const uint32_t*)(sP2 + (p_ + 8) * 72 + kh);
            a2f[2] = *(const uint32_t*)(sP2 + p_ * 72 + kh + 8);
            a2f[3] = *(const uint32_t*)(sP2 + (p_ + 8) * 72 + kh + 8);
            #pragma unroll
            for (int nf = 0; nf < 8; nf++) {
                uint32_t bf[2];
                bf[0] = *(const uint32_t*)(sVts + (nf * 8 + p_) * 72 + kh);
                bf[1] = *(const uint32_t*)(sVts + (nf * 8 + p_) * 72 + kh + 8);
                mma_f16(O1[nf], a1f, bf);
                mma_f16(O2[nf], a2f, bf);
            }
        }
    }

    float rl10 = 1.f / l1[0], rl11 = 1.f / l1[1];
    float rl20 = 1.f / l2[0], rl21 = 1.f / l2[1];
    int row = q0 + wrow0 + p_;
    #pragma unroll
    for (int nf = 0; nf < 8; nf++) {
        int col = h * 64 + nf * 8 + 2 * q_;
        *(__half2*)(cat + (size_t)row * D2 + col)           = __floats2half2_rn(O1[nf][0] * rl10, O1[nf][1] * rl10);
        *(__half2*)(cat + (size_t)(row + 8) * D2 + col)     = __floats2half2_rn(O1[nf][2] * rl11, O1[nf][3] * rl11);
        *(__half2*)(cat + (size_t)row * D2 + D + col)       = __floats2half2_rn(O2[nf][0] * rl20, O2[nf][1] * rl20);
        *(__half2*)(cat + (size_t)(row + 8) * D2 + D + col) = __floats2half2_rn(O2[nf][2] * rl21, O2[nf][3] * rl21);
    }
}

// ---------------- sigmoid mean (flat, full-chip) ----------------
__global__ __launch_bounds__(256) void k_sigsum(const float* __restrict__ lm)
{
    const size_t n4 = (size_t)H * T * T / 4;
    const float4* p = (const float4*)lm;
    float s = 0.f;
    for (size_t i = (size_t)blockIdx.x * 256 + threadIdx.x; i < n4;
         i += (size_t)gridDim.x * 256) {
        float4 v = p[i];
        s += sigf(v.x) + sigf(v.y) + sigf(v.z) + sigf(v.w);
    }
    float tot = blockReduceSum(s);
    if (threadIdx.x == 0) atomicAdd(&g_sigacc, (double)tot);
}

__global__ void k_zero_acc() { g_sigacc = 0.0; }

__global__ void k_write_sp(float* out, int out_size)
{
    const long long TD = (long long)T * D;
    if (out_size > TD) {
        double mean = g_sigacc / ((double)H * (double)T * (double)T);
        out[TD] = (float)(SPARSITY_LAMBDA * mean);
    }
}

// ---------------- launch ----------------
#define HT_SMEM (6 * HT_STAGE * sizeof(__half))  // 61440
#define FL_SMEM 180224

extern "C" void kernel_launch(void* const* d_in, const int* in_sizes, int n_in,
                              void* d_out, int out_size)
{
    const float* x      = (const float*)d_in[0];
    const float* W_qkv  = (const float*)d_in[2];
    const float* W_out  = (const float*)d_in[3];
    const float* logm   = (const float*)d_in[4];
    const float* W_gate = (const float*)d_in[5];
    const float* b_gate = (const float*)d_in[6];
    const float* g1     = (const float*)d_in[7];
    const float* b1     = (const float*)d_in[8];
    const float* g2     = (const float*)d_in[9];
    const float* b2     = (const float*)d_in[10];
    const float* W_ff1  = (const float*)d_in[11];
    const float* b_ff1  = (const float*)d_in[12];
    const float* W_ff2  = (const float*)d_in[13];
    const float* b_ff2  = (const float*)d_in[14];
    float* out = (float*)d_out;

    __half *xnh, *qkvh, *cath, *tmph, *hnh, *ffh;
    __half *wqkvh, *wgateh, *wouth, *wff1h, *wff2h;
    float *hbuf;
    cudaGetSymbolAddress((void**)&xnh,   g_xnh);
    cudaGetSymbolAddress((void**)&qkvh,  g_qkvh);
    cudaGetSymbolAddress((void**)&cath,  g_cath);
    cudaGetSymbolAddress((void**)&tmph,  g_tmph);
    cudaGetSymbolAddress((void**)&hbuf,  g_h);
    cudaGetSymbolAddress((void**)&hnh,   g_hnh);
    cudaGetSymbolAddress((void**)&ffh,   g_ffh);
    cudaGetSymbolAddress((void**)&wqkvh, g_wqkvh);
    cudaGetSymbolAddress((void**)&wgateh, g_wgateh);
    cudaGetSymbolAddress((void**)&wouth, g_wouth);
    cudaGetSymbolAddress((void**)&wff1h, g_wff1h);
    cudaGetSymbolAddress((void**)&wff2h, g_wff2h);

    cudaFuncSetAttribute(k_hgemm_nt<false, false, false, true >, cudaFuncAttributeMaxDynamicSharedMemorySize, HT_SMEM);
    cudaFuncSetAttribute(k_hgemm_nt<false, true,  false, true >, cudaFuncAttributeMaxDynamicSharedMemorySize, HT_SMEM);
    cudaFuncSetAttribute(k_hgemm_nt<false, false, true,  false>, cudaFuncAttributeMaxDynamicSharedMemorySize, HT_SMEM);
    cudaFuncSetAttribute(k_hgemm_nt<true,  true,  false, true >, cudaFuncAttributeMaxDynamicSharedMemorySize, HT_SMEM);
    cudaFuncSetAttribute(k_hgemm_nt<false, true,  true,  false>, cudaFuncAttributeMaxDynamicSharedMemorySize, HT_SMEM);
    cudaFuncSetAttribute(k_flash, cudaFuncAttributeMaxDynamicSharedMemorySize, FL_SMEM);

    k_zero_acc<<<1, 1>>>();

    // weight conversions (fp32 -> fp16)
    k_f2h<<<1184, 256>>>(W_qkv,  wqkvh,  D3 * D / 4);
    k_f2h<<<1184, 256>>>(W_gate, wgateh, D * D2 / 4);
    k_f2h<<<1184, 256>>>(W_out,  wouth,  D * D / 4);
    k_f2h<<<1184, 256>>>(W_ff1,  wff1h,  DFF * D / 4);
    k_f2h<<<1184, 256>>>(W_ff2,  wff2h,  D * DFF / 4);

    // ln1 -> half
    k_layernorm_h<<<T, 256>>>(x, g1, b1, xnh);

    // qkv = xn @ W_qkv^T  (half out; flash is the sole consumer)
    k_hgemm_nt<false, false, false, true><<<dim3(D3 / 128, T / 128), 256, HT_SMEM>>>(
        xnh, D, wqkvh, D, qkvh, D3, D, nullptr, nullptr, 0);

    // sigmoid-mean over the full mask
    k_sigsum<<<1184, 256>>>(logm);

    // fused dual-softmax attention -> cat (half)
    k_flash<<<256, 256, FL_SMEM>>>(qkvh, logm, cath);

    // tmp = cat @ W_gate^T + b_gate  (half out)
    k_hgemm_nt<false, true, false, true><<<dim3(D / 128, T / 128), 256, HT_SMEM>>>(
        cath, D2, wgateh, D2, tmph, D, D2, b_gate, nullptr, 0);

    // h = x + tmp @ W_out^T  (fp32 out)
    k_hgemm_nt<false, false, true, false><<<dim3(D / 128, T / 128), 256, HT_SMEM>>>(
        tmph, D, wouth, D, hbuf, D, D, nullptr, x, D);

    // ln2 -> half
    k_layernorm_h<<<T, 256>>>(hbuf, g2, b2, hnh);

    // ff = gelu(hn @ W_ff1^T + b_ff1)  (half out)
    k_hgemm_nt<true, true, false, true><<<dim3(DFF / 128, T / 128), 256, HT_SMEM>>>(
        hnh, D, wff1h, D, ffh, DFF, D, b_ff1, nullptr, 0);

    // out = h + ff @ W_ff2^T + b_ff2  (fp32 out)
    k_hgemm_nt<false, true, true, false><<<dim3(D / 128, T / 128), 256, HT_SMEM>>>(
        ffh, DFF, wff2h, DFF, out, D, DFF, b_ff2, hbuf, D);

    k_write_sp<<<1, 1>>>(out, out_size);
}